// round 5
// baseline (speedup 1.0000x reference)
#include <cuda_runtime.h>
#include <math.h>
#include <stdint.h>
#include <string.h>

#define NB    2
#define NCAM  6
#define DIM   256
#define HWQ   2500
#define PK    625
#define NHEAD 8
#define DH    32
#define ND    1536

typedef unsigned long long u64;

// ---------------- f32x2 packed math (Blackwell) ----------------
__device__ __forceinline__ u64 ffma2(u64 a, u64 b, u64 c){
    u64 d; asm("fma.rn.f32x2 %0, %1, %2, %3;" : "=l"(d) : "l"(a), "l"(b), "l"(c)); return d;
}
__device__ __forceinline__ u64 fmul2(u64 a, u64 b){
    u64 d; asm("mul.rn.f32x2 %0, %1, %2;" : "=l"(d) : "l"(a), "l"(b)); return d;
}
__device__ __forceinline__ u64 pack2(float x, float y){
    u64 d; asm("mov.b64 %0, {%1, %2};" : "=l"(d) : "f"(x), "f"(y)); return d;
}
__device__ __forceinline__ float2 unpack2(u64 v){
    float2 r; asm("mov.b64 {%0, %1}, %2;" : "=f"(r.x), "=f"(r.y) : "l"(v)); return r;
}
__device__ __forceinline__ float tf32r(float x){
    uint32_t u; asm("cvt.rna.tf32.f32 %0, %1;" : "=r"(u) : "f"(x));
    return __uint_as_float(u);
}
__device__ __forceinline__ uint32_t smem_to_u32(const void* smem_ptr) {
    uint32_t addr;
    asm("{ .reg .u64 tmp; cvta.to.shared.u64 tmp, %1; cvt.u32.u64 %0, tmp; }"
        : "=r"(addr) : "l"(smem_ptr));
    return addr;
}
__device__ __forceinline__ void ldsm_x4(uint32_t& r0, uint32_t& r1, uint32_t& r2, uint32_t& r3, uint32_t addr){
    asm volatile("ldmatrix.sync.aligned.m8n8.x4.shared.b16 {%0,%1,%2,%3}, [%4];"
        : "=r"(r0),"=r"(r1),"=r"(r2),"=r"(r3) : "r"(addr));
}
__device__ __forceinline__ void mma_tf32(float* d, const uint32_t* a, const uint32_t* b){
    asm volatile("mma.sync.aligned.m16n8k8.row.col.f32.tf32.tf32.f32 "
        "{%0,%1,%2,%3}, {%4,%5,%6,%7}, {%8,%9}, {%0,%1,%2,%3};"
        : "+f"(d[0]),"+f"(d[1]),"+f"(d[2]),"+f"(d[3])
        : "r"(a[0]),"r"(a[1]),"r"(a[2]),"r"(a[3]), "r"(b[0]),"r"(b[1]));
}

// ---------------- scratch ----------------
__device__ float g_qT    [(long)NB*HWQ*ND];
__device__ float g_kpool [(long)NB*PK*ND];
__device__ float g_vpool [(long)NB*PK*ND];
__device__ float g_qf    [(long)NB*NCAM*HWQ*DIM];
__device__ float g_kf    [(long)NB*NCAM*PK*DIM];
__device__ float g_vf    [(long)NB*NCAM*PK*DIM];
__device__ float g_addq  [(long)NB*HWQ*DIM];
__device__ float g_attno [(long)NB*HWQ*ND];
__device__ float g_fac   [(long)NB*HWQ*64];
__device__ float g_lnbuf [(long)NB*HWQ*ND];
__device__ float g_xbuf  [(long)NB*HWQ*DIM];
__device__ float g_h1    [(long)NB*HWQ*2*DIM];
__device__ float g_tbuf  [(long)NB*HWQ*DIM];
// transposed + tf32-split weights
#define OFF_WQ    0L
#define OFF_WK    65536L
#define OFF_WV    131072L
#define OFF_WADDQ 196608L
#define OFF_WPROJ 589824L
#define OFF_W1    983040L
#define OFF_W2    1114112L
#define WTOT      1245184L
__device__ float g_whi[WTOT];
__device__ float g_wlo[WTOT];

__device__ __forceinline__ float warpRedSum(float v){
    #pragma unroll
    for (int o=16;o;o>>=1) v += __shfl_xor_sync(0xffffffffu, v, o);
    return v;
}

// ---------------- transpose q: (b,cam,c,p) -> (b,p,cam*256+c) ----------------
__global__ void transpose_q_kernel(const float* __restrict__ q, float* __restrict__ qT){
    __shared__ float tile[32][33];
    int bn  = blockIdx.z;
    int b   = bn / NCAM, cam = bn % NCAM;
    int p0  = blockIdx.x * 32;
    int c0  = blockIdx.y * 32;
    int tx  = threadIdx.x, ty = threadIdx.y;
    #pragma unroll
    for (int i = ty; i < 32; i += 8){
        int c = c0 + i, p = p0 + tx;
        float v = 0.f;
        if (p < HWQ) v = q[((long)bn*DIM + c)*HWQ + p];
        tile[i][tx] = v;
    }
    __syncthreads();
    #pragma unroll
    for (int i = ty; i < 32; i += 8){
        int p = p0 + i, c = c0 + tx;
        if (p < HWQ)
            qT[((long)(b*HWQ + p))*ND + cam*DIM + c] = tile[tx][i];
    }
}

// ---------------- 2x2 pool + transpose ----------------
__global__ void pool_kernel(const float* __restrict__ src, float* __restrict__ dst){
    long idx = (long)blockIdx.x * blockDim.x + threadIdx.x;
    const long total = (long)NB*NCAM*DIM*PK;
    if (idx >= total) return;
    int kk  = (int)(idx % PK);  long t = idx / PK;
    int c   = (int)(t % DIM);   t /= DIM;
    int cam = (int)(t % NCAM);
    int b   = (int)(t / NCAM);
    int i = kk / 25, j = kk % 25;
    const float* p = src + ((long)((b*NCAM+cam)*DIM + c))*HWQ + (2*i)*50 + 2*j;
    float v = 0.25f * (p[0] + p[1] + p[50] + p[51]);
    dst[((long)(b*PK + kk)*NCAM + cam)*DIM + c] = v;
}

// ---------------- weight prep: W[K][N] -> Whi/Wlo [N][K] (transpose + tf32 split) ----
__global__ void wprep_kernel(const float* __restrict__ src, float* __restrict__ hi,
                             float* __restrict__ lo, int K, int N){
    __shared__ float tile[32][33];
    int k0 = blockIdx.x*32, n0 = blockIdx.y*32;
    int tx = threadIdx.x, ty = threadIdx.y;
    #pragma unroll
    for (int i=ty;i<32;i+=8)
        tile[i][tx] = src[(long)(k0+i)*N + n0 + tx];
    __syncthreads();
    #pragma unroll
    for (int i=ty;i<32;i+=8){
        float v = tile[tx][i];
        float h = tf32r(v);
        float l = tf32r(v - h);
        hi[(long)(n0+i)*K + k0+tx] = h;
        lo[(long)(n0+i)*K + k0+tx] = l;
    }
}

// ---------------- 3xTF32 mma.sync GEMM: M128 x N64 tiles, K16 chunks -------------
// A[M][K] f32 (split on the fly), B pre-split hi/lo [N][K] tf32.
// smem row stride 20 floats; chunk permutation pc(r,c) = (c + r + (r>>3)) & 3.
struct TGemmP {
    const float* A; const float* Bhi; const float* Blo;
    const float* bias; const float* Cadd; float* C;
    int lda, ldc;
    int M, N, K;
    int gelu, D1;
    long a0, a1, c0, c1;
};

#define SMS   20          // floats per smem row
#define OFF_AH 0
#define OFF_AL 2560
#define OFF_BH 5120
#define OFF_BL 6400
#define BUF_F  7680       // floats per buffer
#define TG_SMEM (2*BUF_F*4)

__global__ __launch_bounds__(128,2) void tgemm_kernel(TGemmP p){
    extern __shared__ float sm[];
    int tid = threadIdx.x;
    int w = tid >> 5, l = tid & 31;

    int z = blockIdx.z;
    int i1 = z % p.D1, i0 = z / p.D1;
    const float* A = p.A + i0*p.a0 + i1*p.a1;
    float*       C = p.C + i0*p.c0 + i1*p.c1;
    int row0 = blockIdx.y*128, col0 = blockIdx.x*64;

    // fill-side mapping
    int arow = row0 + tid;
    bool av = arow < p.M;
    const float* aptr = A + (av ? (long)arow*p.lda : 0);
    int bn = tid & 63, bwhich = tid >> 6;
    const float* bhp = p.Bhi + (long)(col0+bn)*p.K + bwhich*8;
    const float* blp = p.Blo + (long)(col0+bn)*p.K + bwhich*8;
    int apc[4], bpc0, bpc1;
    #pragma unroll
    for (int j=0;j<4;j++) apc[j] = (j + tid + (tid>>3)) & 3;
    bpc0 = (2*bwhich     + bn + (bn>>3)) & 3;
    bpc1 = (2*bwhich + 1 + bn + (bn>>3)) & 3;

    // ldmatrix-side per-lane constants
    uint32_t smb = smem_to_u32(sm);
    int mat = l >> 3, lr = l & 7;
    int a_r  = w*32 + (mat&1)*8 + lr;   // + mt*16
    int a_chi = mat >> 1;
    int b_n  = (mat>>1)*8 + lr;         // + ntp*16
    int b_cb = mat & 1;

    float acc[2][8][4];
    #pragma unroll
    for (int mt=0;mt<2;mt++)
        #pragma unroll
        for (int nt=0;nt<8;nt++)
            #pragma unroll
            for (int r=0;r<4;r++) acc[mt][nt][r] = 0.f;

    const float4 z4 = make_float4(0.f,0.f,0.f,0.f);
    int NT = p.K / 16;

    // tile fill
    auto fill = [&](int kt, int buf){
        float* base = sm + buf*BUF_F;
        const float* pa = aptr + kt*16;
        #pragma unroll
        for (int j=0;j<4;j++){
            float4 v = av ? *(const float4*)(pa + j*4) : z4;
            float4 h, lo4;
            h.x = tf32r(v.x); lo4.x = tf32r(v.x - h.x);
            h.y = tf32r(v.y); lo4.y = tf32r(v.y - h.y);
            h.z = tf32r(v.z); lo4.z = tf32r(v.z - h.z);
            h.w = tf32r(v.w); lo4.w = tf32r(v.w - h.w);
            *(float4*)(base + OFF_AH + tid*SMS + apc[j]*4) = h;
            *(float4*)(base + OFF_AL + tid*SMS + apc[j]*4) = lo4;
        }
        const float* ph = bhp + kt*16;
        const float* pl = blp + kt*16;
        *(float4*)(base + OFF_BH + bn*SMS + bpc0*4) = *(const float4*)(ph);
        *(float4*)(base + OFF_BH + bn*SMS + bpc1*4) = *(const float4*)(ph + 4);
        *(float4*)(base + OFF_BL + bn*SMS + bpc0*4) = *(const float4*)(pl);
        *(float4*)(base + OFF_BL + bn*SMS + bpc1*4) = *(const float4*)(pl + 4);
    };

    fill(0, 0);
    __syncthreads();

    for (int kt=0; kt<NT; kt++){
        int buf = kt & 1;
        if (kt+1 < NT) fill(kt+1, buf^1);
        uint32_t bb = smb + buf*(BUF_F*4);

        #pragma unroll
        for (int ks=0; ks<2; ks++){
            uint32_t ah[2][4], al[2][4], bh[8][2], bl[8][2];
            #pragma unroll
            for (int mt=0;mt<2;mt++){
                int r = a_r + mt*16;
                int c = (2*ks + a_chi + r + (r>>3)) & 3;
                uint32_t off = (uint32_t)(r*(SMS*4) + c*16);
                ldsm_x4(ah[mt][0],ah[mt][1],ah[mt][2],ah[mt][3], bb + OFF_AH*4 + off);
                ldsm_x4(al[mt][0],al[mt][1],al[mt][2],al[mt][3], bb + OFF_AL*4 + off);
            }
            #pragma unroll
            for (int ntp=0;ntp<4;ntp++){
                int n = b_n + ntp*16;
                int c = (2*ks + b_cb + n + (n>>3)) & 3;
                uint32_t off = (uint32_t)(n*(SMS*4) + c*16);
                ldsm_x4(bh[2*ntp][0],bh[2*ntp][1],bh[2*ntp+1][0],bh[2*ntp+1][1], bb + OFF_BH*4 + off);
                ldsm_x4(bl[2*ntp][0],bl[2*ntp][1],bl[2*ntp+1][0],bl[2*ntp+1][1], bb + OFF_BL*4 + off);
            }
            #pragma unroll
            for (int mt=0;mt<2;mt++)
                #pragma unroll
                for (int nt=0;nt<8;nt++){
                    mma_tf32(acc[mt][nt], ah[mt], bh[nt]);
                    mma_tf32(acc[mt][nt], ah[mt], bl[nt]);
                    mma_tf32(acc[mt][nt], al[mt], bh[nt]);
                }
        }
        __syncthreads();
    }

    // epilogue: c-frag rows g,(g+8), cols t*2,t*2+1
    int g = l >> 2, t = l & 3;
    #pragma unroll
    for (int mt=0;mt<2;mt++){
        #pragma unroll
        for (int nt=0;nt<8;nt++){
            int cc = col0 + nt*8 + t*2;
            float2 bia = make_float2(0.f, 0.f);
            if (p.bias) bia = *(const float2*)(p.bias + cc);
            #pragma unroll
            for (int half=0; half<2; half++){
                int r = row0 + w*32 + mt*16 + g + half*8;
                if (r >= p.M) continue;
                float ox = acc[mt][nt][half*2+0] + bia.x;
                float oy = acc[mt][nt][half*2+1] + bia.y;
                if (p.gelu){ ox *= normcdff(ox); oy *= normcdff(oy); }
                if (p.Cadd){
                    float2 av2 = *(const float2*)(p.Cadd + (long)r*p.ldc + cc);
                    ox += av2.x; oy += av2.y;
                }
                *(float2*)(C + (long)r*p.ldc + cc) = make_float2(ox, oy);
            }
        }
    }
}

// ---------------- fused flash attention, deferred normalization ----------------
__global__ __launch_bounds__(256,2) void flash_kernel(
    const float* __restrict__ qf, const float* __restrict__ kf,
    const float* __restrict__ vf, float* __restrict__ ao, float* __restrict__ fac)
{
    __shared__ float Qs[64][32];
    __shared__ float Ks[64][36];
    __shared__ float Vt[32][68];
    __shared__ float Ps[64][68];

    int zz = blockIdx.y; int b = zz >> 3, m = zz & 7;
    int q0 = blockIdx.x * 64;
    int tid = threadIdx.x, tx = tid & 15, ty = tid >> 4;
    const float scale = 0.17677669529663689f;
    const float4 z4 = make_float4(0.f,0.f,0.f,0.f);

    float mrow[4] = {-1e30f,-1e30f,-1e30f,-1e30f};
    float lrow[4] = {0.f,0.f,0.f,0.f};

    for (int cam=0; cam<6; cam++){
        u64 accA[4], accB[4];
        #pragma unroll
        for (int i=0;i<4;i++){ accA[i]=0ULL; accB[i]=0ULL; }
        const float* qbase = qf + ((long)(b*NCAM+cam)*HWQ)*DIM + m*DH;
        const float* kbase = kf + ((long)(b*NCAM+cam)*PK)*DIM + m*DH;
        const float* vbase = vf + ((long)(b*NCAM+cam)*PK)*DIM + m*DH;

        for (int kt=0; kt<10; kt++){
            int kk0 = kt*64;
            __syncthreads();
            if (kt == 0){
                #pragma unroll
                for (int t=0;t<2;t++){
                    int idx = tid + t*256;
                    int r = idx>>3, c4 = (idx&7)*4;
                    float4 v = z4;
                    if (q0+r < HWQ) v = *(const float4*)(qbase + (long)(q0+r)*DIM + c4);
                    v.x*=scale; v.y*=scale; v.z*=scale; v.w*=scale;
                    *(float4*)&Qs[r][c4] = v;
                }
            }
            #pragma unroll
            for (int t=0;t<2;t++){
                int idx = tid + t*256;
                int r = idx>>3, c4 = (idx&7)*4;
                float4 kv = z4, vv = z4;
                if (kk0 + r < PK){
                    kv = *(const float4*)(kbase + (long)(kk0+r)*DIM + c4);
                    vv = *(const float4*)(vbase + (long)(kk0+r)*DIM + c4);
                }
                *(float4*)&Ks[r][c4] = kv;
                Vt[c4+0][r]=vv.x; Vt[c4+1][r]=vv.y; Vt[c4+2][r]=vv.z; Vt[c4+3][r]=vv.w;
            }
            __syncthreads();

            u64 sacc[4][4];
            #pragma unroll
            for (int i=0;i<4;i++)
                #pragma unroll
                for (int j=0;j<4;j++) sacc[i][j]=0ULL;
            #pragma unroll
            for (int c4=0;c4<8;c4++){
                ulonglong2 qv[4], kv[4];
                #pragma unroll
                for (int i=0;i<4;i++) qv[i] = *(const ulonglong2*)&Qs[ty*4+i][c4*4];
                #pragma unroll
                for (int j=0;j<4;j++) kv[j] = *(const ulonglong2*)&Ks[tx+16*j][c4*4];
                #pragma unroll
                for (int i=0;i<4;i++)
                    #pragma unroll
                    for (int j=0;j<4;j++){
                        sacc[i][j]=ffma2(qv[i].x,kv[j].x,sacc[i][j]);
                        sacc[i][j]=ffma2(qv[i].y,kv[j].y,sacc[i][j]);
                    }
            }
            #pragma unroll
            for (int i=0;i<4;i++){
                float s_[4];
                float tmax = -1e30f;
                #pragma unroll
                for (int j=0;j<4;j++){
                    float2 t2 = unpack2(sacc[i][j]);
                    float s = t2.x + t2.y;
                    if (kk0 + tx + 16*j >= PK) s = -1e30f;
                    s_[j] = s; tmax = fmaxf(tmax, s);
                }
                #pragma unroll
                for (int off=1; off<16; off<<=1)
                    tmax = fmaxf(tmax, __shfl_xor_sync(0xffffffffu, tmax, off));
                float mnew = fmaxf(mrow[i], tmax);
                float corr = __expf(mrow[i] - mnew);
                float rsum = 0.f;
                #pragma unroll
                for (int j=0;j<4;j++){
                    float pv = __expf(s_[j] - mnew);
                    rsum += pv;
                    Ps[ty*4+i][tx+16*j] = pv;
                }
                #pragma unroll
                for (int off=1; off<16; off<<=1)
                    rsum += __shfl_xor_sync(0xffffffffu, rsum, off);
                lrow[i] = lrow[i]*corr + rsum;
                mrow[i] = mnew;
                u64 cp = pack2(corr, corr);
                accA[i] = fmul2(accA[i], cp);
                accB[i] = fmul2(accB[i], cp);
            }
            __syncthreads();

            #pragma unroll
            for (int k4=0;k4<16;k4++){
                ulonglong2 va = *(const ulonglong2*)&Vt[tx][k4*4];
                ulonglong2 vb = *(const ulonglong2*)&Vt[tx+16][k4*4];
                #pragma unroll
                for (int i=0;i<4;i++){
                    ulonglong2 pp = *(const ulonglong2*)&Ps[ty*4+i][k4*4];
                    accA[i]=ffma2(pp.x,va.x,accA[i]); accA[i]=ffma2(pp.y,va.y,accA[i]);
                    accB[i]=ffma2(pp.x,vb.x,accB[i]); accB[i]=ffma2(pp.y,vb.y,accB[i]);
                }
            }
        }
        #pragma unroll
        for (int i=0;i<4;i++){
            int qrow = q0 + ty*4 + i;
            if (qrow >= HWQ) continue;
            float2 a = unpack2(accA[i]);
            float2 v2 = unpack2(accB[i]);
            long rowoff = ((long)b*HWQ + qrow)*ND + cam*DIM + m*DH;
            ao[rowoff + tx]      = a.x + a.y;
            ao[rowoff + tx + 16] = v2.x + v2.y;
            if (tx == 0)
                fac[((long)(b*HWQ+qrow))*64 + cam*8 + m] = mrow[i];
        }
    }
    #pragma unroll
    for (int i=0;i<4;i++){
        int qrow = q0 + ty*4 + i;
        if (qrow >= HWQ || tx != 0) continue;
        long f0 = ((long)(b*HWQ+qrow))*64;
        fac[f0 + 48 + m] = mrow[i];
        fac[f0 + 56 + m] = lrow[i];
    }
}

// ---------------- layernorm over 1536 with deferred softmax normalization ----
__global__ void ln1536_kernel(const float* __restrict__ x, const float* __restrict__ fac,
                              const float* __restrict__ g, const float* __restrict__ b,
                              float* __restrict__ y){
    __shared__ float sh[8];
    __shared__ float bmu, brs;
    __shared__ float f48[48];
    long row = blockIdx.x;
    const float* p = x + row * (long)ND;
    const float* fr = fac + row * 64;
    int tid = threadIdx.x;
    if (tid < 48){
        int mm = tid & 7;
        f48[tid] = __expf(fr[tid] - fr[48+mm]) / fr[56+mm];
    }
    __syncthreads();
    float vals[6]; float s = 0.f;
    #pragma unroll
    for (int i=0;i<6;i++){
        int c = tid + i*256;
        float fv = f48[((c>>8)<<3) + ((c>>5)&7)];
        vals[i] = p[c] * fv; s += vals[i];
    }
    s = warpRedSum(s);
    if ((tid & 31) == 0) sh[tid>>5] = s;
    __syncthreads();
    if (tid == 0){ float t=0.f; for (int i=0;i<8;i++) t += sh[i]; bmu = t / (float)ND; }
    __syncthreads();
    float mu = bmu, vs = 0.f;
    #pragma unroll
    for (int i=0;i<6;i++){ float d = vals[i]-mu; vs += d*d; }
    vs = warpRedSum(vs);
    if ((tid & 31) == 0) sh[tid>>5] = vs;
    __syncthreads();
    if (tid == 0){ float t=0.f; for (int i=0;i<8;i++) t += sh[i]; brs = rsqrtf(t/(float)ND + 1e-5f); }
    __syncthreads();
    float rs = brs;
    float* q = y + row * (long)ND;
    #pragma unroll
    for (int i=0;i<6;i++){ int c = tid + i*256; q[c] = (vals[i]-mu)*rs*g[c] + b[c]; }
}

// ---------------- final: LN(t) + x, transpose to (B,d,H,W) ----------------
__global__ void final_kernel(const float* __restrict__ t, const float* __restrict__ x,
                             const float* __restrict__ g, const float* __restrict__ bb,
                             float* __restrict__ out){
    __shared__ float sh[8];
    __shared__ float bmu, brs;
    long row = blockIdx.x;
    int c = threadIdx.x;
    float v = t[row*(long)DIM + c];
    float s = warpRedSum(v);
    if ((c & 31) == 0) sh[c>>5] = s;
    __syncthreads();
    if (c == 0){ float m=0.f; for (int i=0;i<8;i++) m += sh[i]; bmu = m / (float)DIM; }
    __syncthreads();
    float mu = bmu;
    float d = v - mu;
    float vs = warpRedSum(d*d);
    if ((c & 31) == 0) sh[c>>5] = vs;
    __syncthreads();
    if (c == 0){ float m=0.f; for (int i=0;i<8;i++) m += sh[i]; brs = rsqrtf(m/(float)DIM + 1e-5f); }
    __syncthreads();
    float y = d * brs * g[c] + bb[c] + x[row*(long)DIM + c];
    int b = (int)(row / HWQ), p = (int)(row % HWQ);
    out[((long)(b*DIM + c))*HWQ + p] = y;
}

// ---------------- host ----------------
static float* sym(const void* symbol){
    void* p = nullptr;
    cudaGetSymbolAddress(&p, symbol);
    return (float*)p;
}

static TGemmP zeroP(){ TGemmP p; memset(&p, 0, sizeof(p)); p.D1 = 1; return p; }

static void launch_tgemm(const TGemmP& p, int batches){
    dim3 grid(p.N/64, (p.M+127)/128, batches);
    tgemm_kernel<<<grid, 128, TG_SMEM>>>(p);
}

extern "C" void kernel_launch(void* const* d_in, const int* in_sizes, int n_in,
                              void* d_out, int out_size){
    const float* q     = (const float*)d_in[0];
    const float* k     = (const float*)d_in[1];
    const float* v     = (const float*)d_in[2];
    const float* Wq    = (const float*)d_in[3];
    const float* bq    = (const float*)d_in[4];
    const float* Wk    = (const float*)d_in[5];
    const float* bk    = (const float*)d_in[6];
    const float* Wv    = (const float*)d_in[7];
    const float* bv    = (const float*)d_in[8];
    const float* Wproj = (const float*)d_in[9];
    const float* bproj = (const float*)d_in[10];
    const float* Waddq = (const float*)d_in[11];
    const float* baddq = (const float*)d_in[12];
    const float* W1    = (const float*)d_in[13];
    const float* b1    = (const float*)d_in[14];
    const float* W2    = (const float*)d_in[15];
    const float* b2    = (const float*)d_in[16];
    const float* g_pre = (const float*)d_in[17];
    const float* b_pre = (const float*)d_in[18];
    const float* g_nrm = (const float*)d_in[19];
    const float* b_nrm = (const float*)d_in[20];
    float* out = (float*)d_out;

    float* qT    = sym(g_qT);
    float* kpool = sym(g_kpool);
    float* vpool = sym(g_vpool);
    float* qf    = sym(g_qf);
    float* kf    = sym(g_kf);
    float* vf    = sym(g_vf);
    float* addq  = sym(g_addq);
    float* ao    = sym(g_attno);
    float* fac   = sym(g_fac);
    float* lnb   = sym(g_lnbuf);
    float* xb    = sym(g_xbuf);
    float* h1    = sym(g_h1);
    float* tb    = sym(g_tbuf);
    float* whi   = sym(g_whi);
    float* wlo   = sym(g_wlo);

    cudaFuncSetAttribute(tgemm_kernel, cudaFuncAttributeMaxDynamicSharedMemorySize, TG_SMEM);

    // 1) transpose q -> (b,p,nd)
    {
        dim3 grid((HWQ+31)/32, DIM/32, NB*NCAM);
        transpose_q_kernel<<<grid, dim3(32,8)>>>(q, qT);
    }
    // 2) pool k, v
    {
        long total = (long)NB*NCAM*DIM*PK;
        int blocks = (int)((total + 255) / 256);
        pool_kernel<<<blocks, 256>>>(k, kpool);
        pool_kernel<<<blocks, 256>>>(v, vpool);
    }
    // 2b) weight prep (transpose + tf32 split)
    {
        dim3 blk(32,8);
        wprep_kernel<<<dim3(DIM/32, DIM/32), blk>>>(Wq,    whi+OFF_WQ,    wlo+OFF_WQ,    DIM, DIM);
        wprep_kernel<<<dim3(DIM/32, DIM/32), blk>>>(Wk,    whi+OFF_WK,    wlo+OFF_WK,    DIM, DIM);
        wprep_kernel<<<dim3(DIM/32, DIM/32), blk>>>(Wv,    whi+OFF_WV,    wlo+OFF_WV,    DIM, DIM);
        wprep_kernel<<<dim3(ND/32,  DIM/32), blk>>>(Waddq, whi+OFF_WADDQ, wlo+OFF_WADDQ, ND,  DIM);
        wprep_kernel<<<dim3(ND/32,  DIM/32), blk>>>(Wproj, whi+OFF_WPROJ, wlo+OFF_WPROJ, ND,  DIM);
        wprep_kernel<<<dim3(DIM/32, 2*DIM/32), blk>>>(W1,  whi+OFF_W1,    wlo+OFF_W1,    DIM, 2*DIM);
        wprep_kernel<<<dim3(2*DIM/32, DIM/32), blk>>>(W2,  whi+OFF_W2,    wlo+OFF_W2,    2*DIM, DIM);
    }
    // 3) add_q = qT @ Waddq + baddq
    {
        TGemmP p = zeroP();
        p.A = qT; p.lda = ND; p.Bhi = whi+OFF_WADDQ; p.Blo = wlo+OFF_WADDQ; p.bias = baddq;
        p.C = addq; p.ldc = DIM; p.M = NB*HWQ; p.N = DIM; p.K = ND;
        launch_tgemm(p, 1);
    }
    // 4) qf per (b,cam)
    {
        TGemmP p = zeroP();
        p.A = qT; p.lda = ND; p.a0 = (long)HWQ*ND; p.a1 = DIM;
        p.Bhi = whi+OFF_WQ; p.Blo = wlo+OFF_WQ; p.bias = bq;
        p.C = qf; p.ldc = DIM; p.c0 = (long)NCAM*HWQ*DIM; p.c1 = (long)HWQ*DIM;
        p.M = HWQ; p.N = DIM; p.K = DIM; p.D1 = NCAM;
        launch_tgemm(p, NB*NCAM);
    }
    // 5) kf, vf per (b,cam)
    {
        TGemmP p = zeroP();
        p.A = kpool; p.lda = ND; p.a0 = (long)PK*ND; p.a1 = DIM;
        p.Bhi = whi+OFF_WK; p.Blo = wlo+OFF_WK; p.bias = bk;
        p.C = kf; p.ldc = DIM; p.c0 = (long)NCAM*PK*DIM; p.c1 = (long)PK*DIM;
        p.M = PK; p.N = DIM; p.K = DIM; p.D1 = NCAM;
        launch_tgemm(p, NB*NCAM);
        p.A = vpool; p.Bhi = whi+OFF_WV; p.Blo = wlo+OFF_WV; p.bias = bv; p.C = vf;
        launch_tgemm(p, NB*NCAM);
    }
    // 6) fused flash attention -> ao partials + fac
    {
        dim3 grid((HWQ+63)/64, NB*NHEAD);
        flash_kernel<<<grid, 256>>>(qf, kf, vf, ao, fac);
    }
    // 7) pre-layernorm (applies deferred softmax normalization)
    ln1536_kernel<<<NB*HWQ, 256>>>(ao, fac, g_pre, b_pre, lnb);
    // 8) xb = LN(out) @ Wproj + bproj + addq
    {
        TGemmP p = zeroP();
        p.A = lnb; p.lda = ND; p.Bhi = whi+OFF_WPROJ; p.Blo = wlo+OFF_WPROJ; p.bias = bproj;
        p.Cadd = addq;
        p.C = xb; p.ldc = DIM; p.M = NB*HWQ; p.N = DIM; p.K = ND;
        launch_tgemm(p, 1);
    }
    // 9) h1 = gelu(xb @ W1 + b1)
    {
        TGemmP p = zeroP();
        p.A = xb; p.lda = DIM; p.Bhi = whi+OFF_W1; p.Blo = wlo+OFF_W1; p.bias = b1; p.gelu = 1;
        p.C = h1; p.ldc = 2*DIM; p.M = NB*HWQ; p.N = 2*DIM; p.K = DIM;
        launch_tgemm(p, 1);
    }
    // 10) tb = h1 @ W2 + b2
    {
        TGemmP p = zeroP();
        p.A = h1; p.lda = 2*DIM; p.Bhi = whi+OFF_W2; p.Blo = wlo+OFF_W2; p.bias = b2;
        p.C = tb; p.ldc = DIM; p.M = NB*HWQ; p.N = DIM; p.K = 2*DIM;
        launch_tgemm(p, 1);
    }
    // 11) out = transpose(x + LN(tb))
    final_kernel<<<NB*HWQ, 256>>>(tb, xb, g_nrm, b_nrm, out);
}

// round 6
// speedup vs baseline: 1.3385x; 1.3385x over previous
#include <cuda_runtime.h>
#include <math.h>
#include <string.h>

#define NB    2
#define NCAM  6
#define DIM   256
#define HWQ   2500
#define PK    625
#define NHEAD 8
#define DH    32
#define ND    1536

typedef unsigned long long u64;

// ---------------- f32x2 packed math (Blackwell) ----------------
__device__ __forceinline__ u64 ffma2(u64 a, u64 b, u64 c){
    u64 d; asm("fma.rn.f32x2 %0, %1, %2, %3;" : "=l"(d) : "l"(a), "l"(b), "l"(c)); return d;
}
__device__ __forceinline__ u64 fmul2(u64 a, u64 b){
    u64 d; asm("mul.rn.f32x2 %0, %1, %2;" : "=l"(d) : "l"(a), "l"(b)); return d;
}
__device__ __forceinline__ u64 pack2(float x, float y){
    u64 d; asm("mov.b64 %0, {%1, %2};" : "=l"(d) : "f"(x), "f"(y)); return d;
}
__device__ __forceinline__ float2 unpack2(u64 v){
    float2 r; asm("mov.b64 {%0, %1}, %2;" : "=f"(r.x), "=f"(r.y) : "l"(v)); return r;
}

// ---------------- scratch ----------------
__device__ float g_qT    [(long)NB*HWQ*ND];
__device__ float g_kpool [(long)NB*PK*ND];
__device__ float g_vpool [(long)NB*PK*ND];
__device__ float g_qf    [(long)NB*NCAM*HWQ*DIM];
__device__ float g_kf    [(long)NB*NCAM*PK*DIM];
__device__ float g_vf    [(long)NB*NCAM*PK*DIM];
__device__ float g_attno [(long)NB*HWQ*ND];
__device__ float g_fac   [(long)NB*HWQ*64];
__device__ float g_lnbuf [(long)NB*HWQ*ND];
__device__ float g_xbuf  [(long)NB*HWQ*DIM];
__device__ float g_h1    [(long)NB*HWQ*2*DIM];
__device__ float g_part1 [(long)3*NB*HWQ*DIM];
__device__ float g_part2 [(long)3*NB*HWQ*DIM];
__device__ float g_part3 [(long)2*NB*HWQ*DIM];

__device__ __forceinline__ float warpRedSum(float v){
    #pragma unroll
    for (int o=16;o;o>>=1) v += __shfl_xor_sync(0xffffffffu, v, o);
    return v;
}

// ---------------- transpose q: (b,cam,c,p) -> (b,p,cam*256+c) ----------------
__global__ void transpose_q_kernel(const float* __restrict__ q, float* __restrict__ qT){
    __shared__ float tile[32][33];
    int bn  = blockIdx.z;
    int b   = bn / NCAM, cam = bn % NCAM;
    int p0  = blockIdx.x * 32;
    int c0  = blockIdx.y * 32;
    int tx  = threadIdx.x, ty = threadIdx.y;
    #pragma unroll
    for (int i = ty; i < 32; i += 8){
        int c = c0 + i, p = p0 + tx;
        float v = 0.f;
        if (p < HWQ) v = q[((long)bn*DIM + c)*HWQ + p];
        tile[i][tx] = v;
    }
    __syncthreads();
    #pragma unroll
    for (int i = ty; i < 32; i += 8){
        int p = p0 + i, c = c0 + tx;
        if (p < HWQ)
            qT[((long)(b*HWQ + p))*ND + cam*DIM + c] = tile[tx][i];
    }
}

// ---------------- 2x2 pool + transpose ----------------
__global__ void pool_kernel(const float* __restrict__ src, float* __restrict__ dst){
    long idx = (long)blockIdx.x * blockDim.x + threadIdx.x;
    const long total = (long)NB*NCAM*DIM*PK;
    if (idx >= total) return;
    int kk  = (int)(idx % PK);  long t = idx / PK;
    int c   = (int)(t % DIM);   t /= DIM;
    int cam = (int)(t % NCAM);
    int b   = (int)(t / NCAM);
    int i = kk / 25, j = kk % 25;
    const float* p = src + ((long)((b*NCAM+cam)*DIM + c))*HWQ + (2*i)*50 + 2*j;
    float v = 0.25f * (p[0] + p[1] + p[50] + p[51]);
    dst[((long)(b*PK + kk)*NCAM + cam)*DIM + c] = v;
}

// ---------------- dense GEMM: 128 thr, BM128/BN64/BK16, 8x8/thread, split-K ----
struct GemmP {
    const float* A; const float* B; const float* bias; float* C;
    int lda, ldb, ldc;
    int M, N, K;            // K = per-split span
    int gelu, D1, SPLIT;
    long a0, a1, c0, c1, csplit;
};

__global__ __launch_bounds__(128,4) void gemm_tc(GemmP p){
    __shared__ float As[2][16][128];
    __shared__ float Bs[2][16][64];

    int z = blockIdx.z;
    int s = z % p.SPLIT; int zz = z / p.SPLIT;
    int i1 = zz % p.D1;  int i0 = zz / p.D1;
    const float* A = p.A + i0*p.a0 + i1*p.a1 + (long)s*p.K;
    const float* B = p.B + (long)s*p.K*p.ldb;
    float*       C = p.C + i0*p.c0 + i1*p.c1 + (long)s*p.csplit;

    int tid = threadIdx.x;
    int tx = tid & 7, ty = tid >> 3;
    int row0 = blockIdx.y*128, col0 = blockIdx.x*64;

    int arow = row0 + tid;
    int brow = tid >> 3;
    int bc0  = (tid & 7) * 2;
    int pb0  = (bc0 ^ (bc0 >> 3)) * 4;
    int pb1  = ((bc0+1) ^ ((bc0+1) >> 3)) * 4;

    u64 acc[8][4];
    #pragma unroll
    for (int i=0;i<8;i++)
        #pragma unroll
        for (int j=0;j<4;j++) acc[i][j] = 0ULL;

    const float4 z4 = make_float4(0.f,0.f,0.f,0.f);
    float4 ra[4], rb0, rb1;

    int nt = p.K / 16;
    if (arow < p.M){
        const float* pa = A + (long)arow*p.lda;
        ra[0]=*(const float4*)pa; ra[1]=*(const float4*)(pa+4);
        ra[2]=*(const float4*)(pa+8); ra[3]=*(const float4*)(pa+12);
    } else { ra[0]=z4; ra[1]=z4; ra[2]=z4; ra[3]=z4; }
    {
        const float* pb = B + (long)brow*p.ldb + col0 + bc0*4;
        rb0 = *(const float4*)pb; rb1 = *(const float4*)(pb+4);
    }
    {
        #pragma unroll
        for (int j=0;j<4;j++){
            As[0][j*4+0][tid]=ra[j].x; As[0][j*4+1][tid]=ra[j].y;
            As[0][j*4+2][tid]=ra[j].z; As[0][j*4+3][tid]=ra[j].w;
        }
        *(float4*)&Bs[0][brow][pb0] = rb0;
        *(float4*)&Bs[0][brow][pb1] = rb1;
    }
    __syncthreads();
    int cur = 0;
    for (int t=0; t<nt; t++){
        if (t+1 < nt){
            int k0 = (t+1)*16;
            if (arow < p.M){
                const float* pa = A + (long)arow*p.lda + k0;
                ra[0]=*(const float4*)pa; ra[1]=*(const float4*)(pa+4);
                ra[2]=*(const float4*)(pa+8); ra[3]=*(const float4*)(pa+12);
            } else { ra[0]=z4; ra[1]=z4; ra[2]=z4; ra[3]=z4; }
            const float* pb = B + (long)(k0+brow)*p.ldb + col0 + bc0*4;
            rb0 = *(const float4*)pb; rb1 = *(const float4*)(pb+4);
        }
        #pragma unroll
        for (int kk=0; kk<16; kk++){
            float4 a0 = *(const float4*)&As[cur][kk][ty*8];
            float4 a1 = *(const float4*)&As[cur][kk][ty*8+4];
            ulonglong2 b0 = *(const ulonglong2*)&Bs[cur][kk][pb0];
            ulonglong2 b1 = *(const ulonglong2*)&Bs[cur][kk][pb1];
            u64 ap;
            ap=pack2(a0.x,a0.x); acc[0][0]=ffma2(ap,b0.x,acc[0][0]); acc[0][1]=ffma2(ap,b0.y,acc[0][1]); acc[0][2]=ffma2(ap,b1.x,acc[0][2]); acc[0][3]=ffma2(ap,b1.y,acc[0][3]);
            ap=pack2(a0.y,a0.y); acc[1][0]=ffma2(ap,b0.x,acc[1][0]); acc[1][1]=ffma2(ap,b0.y,acc[1][1]); acc[1][2]=ffma2(ap,b1.x,acc[1][2]); acc[1][3]=ffma2(ap,b1.y,acc[1][3]);
            ap=pack2(a0.z,a0.z); acc[2][0]=ffma2(ap,b0.x,acc[2][0]); acc[2][1]=ffma2(ap,b0.y,acc[2][1]); acc[2][2]=ffma2(ap,b1.x,acc[2][2]); acc[2][3]=ffma2(ap,b1.y,acc[2][3]);
            ap=pack2(a0.w,a0.w); acc[3][0]=ffma2(ap,b0.x,acc[3][0]); acc[3][1]=ffma2(ap,b0.y,acc[3][1]); acc[3][2]=ffma2(ap,b1.x,acc[3][2]); acc[3][3]=ffma2(ap,b1.y,acc[3][3]);
            ap=pack2(a1.x,a1.x); acc[4][0]=ffma2(ap,b0.x,acc[4][0]); acc[4][1]=ffma2(ap,b0.y,acc[4][1]); acc[4][2]=ffma2(ap,b1.x,acc[4][2]); acc[4][3]=ffma2(ap,b1.y,acc[4][3]);
            ap=pack2(a1.y,a1.y); acc[5][0]=ffma2(ap,b0.x,acc[5][0]); acc[5][1]=ffma2(ap,b0.y,acc[5][1]); acc[5][2]=ffma2(ap,b1.x,acc[5][2]); acc[5][3]=ffma2(ap,b1.y,acc[5][3]);
            ap=pack2(a1.z,a1.z); acc[6][0]=ffma2(ap,b0.x,acc[6][0]); acc[6][1]=ffma2(ap,b0.y,acc[6][1]); acc[6][2]=ffma2(ap,b1.x,acc[6][2]); acc[6][3]=ffma2(ap,b1.y,acc[6][3]);
            ap=pack2(a1.w,a1.w); acc[7][0]=ffma2(ap,b0.x,acc[7][0]); acc[7][1]=ffma2(ap,b0.y,acc[7][1]); acc[7][2]=ffma2(ap,b1.x,acc[7][2]); acc[7][3]=ffma2(ap,b1.y,acc[7][3]);
        }
        if (t+1 < nt){
            int nb = cur ^ 1;
            #pragma unroll
            for (int j=0;j<4;j++){
                As[nb][j*4+0][tid]=ra[j].x; As[nb][j*4+1][tid]=ra[j].y;
                As[nb][j*4+2][tid]=ra[j].z; As[nb][j*4+3][tid]=ra[j].w;
            }
            *(float4*)&Bs[nb][brow][pb0] = rb0;
            *(float4*)&Bs[nb][brow][pb1] = rb1;
            __syncthreads();
            cur = nb;
        }
    }
    int colb = col0 + tx*8;
    float4 bia0, bia1;
    if (p.SPLIT == 1 && p.bias){
        bia0 = *(const float4*)(p.bias + colb);
        bia1 = *(const float4*)(p.bias + colb + 4);
    } else { bia0 = z4; bia1 = z4; }
    #pragma unroll
    for (int i=0;i<8;i++){
        int r = row0 + ty*8 + i;
        if (r >= p.M) continue;
        float2 v0 = unpack2(acc[i][0]), v1 = unpack2(acc[i][1]);
        float2 v2 = unpack2(acc[i][2]), v3 = unpack2(acc[i][3]);
        float4 o0 = make_float4(v0.x+bia0.x, v0.y+bia0.y, v1.x+bia0.z, v1.y+bia0.w);
        float4 o1 = make_float4(v2.x+bia1.x, v2.y+bia1.y, v3.x+bia1.z, v3.y+bia1.w);
        if (p.gelu){
            o0.x*=normcdff(o0.x); o0.y*=normcdff(o0.y); o0.z*=normcdff(o0.z); o0.w*=normcdff(o0.w);
            o1.x*=normcdff(o1.x); o1.y*=normcdff(o1.y); o1.z*=normcdff(o1.z); o1.w*=normcdff(o1.w);
        }
        *(float4*)(C + (long)r*p.ldc + colb)     = o0;
        *(float4*)(C + (long)r*p.ldc + colb + 4) = o1;
    }
}

// ---------------- fused flash attention: pipelined K/V, deferred normalization ----
__global__ __launch_bounds__(256,2) void flash_kernel(
    const float* __restrict__ qf, const float* __restrict__ kf,
    const float* __restrict__ vf, float* __restrict__ ao, float* __restrict__ fac)
{
    __shared__ float Qs[64][32];
    __shared__ float Ks[2][64][36];
    __shared__ float Vt[2][32][68];
    __shared__ float Ps[64][68];

    int zz = blockIdx.y; int b = zz >> 3, m = zz & 7;
    int q0 = blockIdx.x * 64;
    int tid = threadIdx.x, tx = tid & 15, ty = tid >> 4;
    const float scale = 0.17677669529663689f;
    const float4 z4 = make_float4(0.f,0.f,0.f,0.f);

    // per-thread fill coordinates (2 chunks of 256 threads cover 64 rows x 32 cols)
    int fr0 = tid >> 3,        fc0 = (tid & 7) * 4;          // chunk 0
    int fr1 = (tid + 256) >> 3, fc1 = fc0;                   // chunk 1
    bool qv0 = (q0 + fr0) < HWQ, qv1 = (q0 + fr1) < HWQ;

    const float* qb0 = qf + ((long)(b*NCAM)*HWQ)*DIM + m*DH;   // cam stride HWQ*DIM
    const float* kb0 = kf + ((long)(b*NCAM)*PK)*DIM + m*DH;
    const float* vb0 = vf + ((long)(b*NCAM)*PK)*DIM + m*DH;
    const long QCAM = (long)HWQ*DIM, KCAM = (long)PK*DIM;

    float mrow[4] = {-1e30f,-1e30f,-1e30f,-1e30f};
    float lrow[4] = {0.f,0.f,0.f,0.f};

    float4 qr0, qr1, kr0, kr1, vr0, vr1;

    // initial prefetch: Q(cam0) + K/V(cam0, tile0)
    {
        qr0 = qv0 ? *(const float4*)(qb0 + (long)(q0+fr0)*DIM + fc0) : z4;
        qr1 = qv1 ? *(const float4*)(qb0 + (long)(q0+fr1)*DIM + fc1) : z4;
        kr0 = *(const float4*)(kb0 + (long)fr0*DIM + fc0);
        vr0 = *(const float4*)(vb0 + (long)fr0*DIM + fc0);
        kr1 = *(const float4*)(kb0 + (long)fr1*DIM + fc1);
        vr1 = *(const float4*)(vb0 + (long)fr1*DIM + fc1);
    }
    // stage
    {
        qr0.x*=scale; qr0.y*=scale; qr0.z*=scale; qr0.w*=scale;
        qr1.x*=scale; qr1.y*=scale; qr1.z*=scale; qr1.w*=scale;
        *(float4*)&Qs[fr0][fc0] = qr0;
        *(float4*)&Qs[fr1][fc1] = qr1;
        *(float4*)&Ks[0][fr0][fc0] = kr0;
        *(float4*)&Ks[0][fr1][fc1] = kr1;
        Vt[0][fc0+0][fr0]=vr0.x; Vt[0][fc0+1][fr0]=vr0.y; Vt[0][fc0+2][fr0]=vr0.z; Vt[0][fc0+3][fr0]=vr0.w;
        Vt[0][fc1+0][fr1]=vr1.x; Vt[0][fc1+1][fr1]=vr1.y; Vt[0][fc1+2][fr1]=vr1.z; Vt[0][fc1+3][fr1]=vr1.w;
    }
    __syncthreads();

    for (int cam=0; cam<6; cam++){
        u64 accA[4], accB[4];
        #pragma unroll
        for (int i=0;i<4;i++){ accA[i]=0ULL; accB[i]=0ULL; }

        for (int kt=0; kt<10; kt++){
            int cur = kt & 1;
            bool lastk = (kt == 9);
            bool havePf = (!lastk) || (cam < 5);
            // ---- prefetch next tile (regs only) ----
            if (!lastk){
                int kk0 = (kt+1)*64;
                const float* kb = kb0 + cam*KCAM;
                const float* vb = vb0 + cam*KCAM;
                bool v0ok = (kk0 + fr0) < PK, v1ok = (kk0 + fr1) < PK;
                kr0 = v0ok ? *(const float4*)(kb + (long)(kk0+fr0)*DIM + fc0) : z4;
                vr0 = v0ok ? *(const float4*)(vb + (long)(kk0+fr0)*DIM + fc0) : z4;
                kr1 = v1ok ? *(const float4*)(kb + (long)(kk0+fr1)*DIM + fc1) : z4;
                vr1 = v1ok ? *(const float4*)(vb + (long)(kk0+fr1)*DIM + fc1) : z4;
            } else if (cam < 5){
                const float* kb = kb0 + (cam+1)*KCAM;
                const float* vb = vb0 + (cam+1)*KCAM;
                const float* qb = qb0 + (cam+1)*QCAM;
                kr0 = *(const float4*)(kb + (long)fr0*DIM + fc0);
                vr0 = *(const float4*)(vb + (long)fr0*DIM + fc0);
                kr1 = *(const float4*)(kb + (long)fr1*DIM + fc1);
                vr1 = *(const float4*)(vb + (long)fr1*DIM + fc1);
                qr0 = qv0 ? *(const float4*)(qb + (long)(q0+fr0)*DIM + fc0) : z4;
                qr1 = qv1 ? *(const float4*)(qb + (long)(q0+fr1)*DIM + fc1) : z4;
            }

            // ---- QK on buffer cur ----
            int kk0 = kt*64;
            u64 sacc[4][4];
            #pragma unroll
            for (int i=0;i<4;i++)
                #pragma unroll
                for (int j=0;j<4;j++) sacc[i][j]=0ULL;
            #pragma unroll
            for (int c4=0;c4<8;c4++){
                ulonglong2 qv[4], kv[4];
                #pragma unroll
                for (int i=0;i<4;i++) qv[i] = *(const ulonglong2*)&Qs[ty*4+i][c4*4];
                #pragma unroll
                for (int j=0;j<4;j++) kv[j] = *(const ulonglong2*)&Ks[cur][tx+16*j][c4*4];
                #pragma unroll
                for (int i=0;i<4;i++)
                    #pragma unroll
                    for (int j=0;j<4;j++){
                        sacc[i][j]=ffma2(qv[i].x,kv[j].x,sacc[i][j]);
                        sacc[i][j]=ffma2(qv[i].y,kv[j].y,sacc[i][j]);
                    }
            }
            // ---- online softmax ----
            #pragma unroll
            for (int i=0;i<4;i++){
                float s_[4];
                float tmax = -1e30f;
                #pragma unroll
                for (int j=0;j<4;j++){
                    float2 t2 = unpack2(sacc[i][j]);
                    float s = t2.x + t2.y;
                    if (kk0 + tx + 16*j >= PK) s = -1e30f;
                    s_[j] = s; tmax = fmaxf(tmax, s);
                }
                #pragma unroll
                for (int off=1; off<16; off<<=1)
                    tmax = fmaxf(tmax, __shfl_xor_sync(0xffffffffu, tmax, off));
                float mnew = fmaxf(mrow[i], tmax);
                float corr = __expf(mrow[i] - mnew);
                float rsum = 0.f;
                #pragma unroll
                for (int j=0;j<4;j++){
                    float pv = __expf(s_[j] - mnew);
                    rsum += pv;
                    Ps[ty*4+i][tx+16*j] = pv;
                }
                #pragma unroll
                for (int off=1; off<16; off<<=1)
                    rsum += __shfl_xor_sync(0xffffffffu, rsum, off);
                lrow[i] = lrow[i]*corr + rsum;
                mrow[i] = mnew;
                u64 cp = pack2(corr, corr);
                accA[i] = fmul2(accA[i], cp);
                accB[i] = fmul2(accB[i], cp);
            }
            __syncthreads();   // Ps visible; all warps past QK(kt)

            // ---- PV on buffer cur ----
            #pragma unroll
            for (int k4=0;k4<16;k4++){
                ulonglong2 va = *(const ulonglong2*)&Vt[cur][tx][k4*4];
                ulonglong2 vb = *(const ulonglong2*)&Vt[cur][tx+16][k4*4];
                #pragma unroll
                for (int i=0;i<4;i++){
                    ulonglong2 pp = *(const ulonglong2*)&Ps[ty*4+i][k4*4];
                    accA[i]=ffma2(pp.x,va.x,accA[i]); accA[i]=ffma2(pp.y,va.y,accA[i]);
                    accB[i]=ffma2(pp.x,vb.x,accB[i]); accB[i]=ffma2(pp.y,vb.y,accB[i]);
                }
            }

            // ---- stage prefetched tile into buffer cur^1 ----
            if (havePf){
                int nb = cur ^ 1;
                *(float4*)&Ks[nb][fr0][fc0] = kr0;
                *(float4*)&Ks[nb][fr1][fc1] = kr1;
                Vt[nb][fc0+0][fr0]=vr0.x; Vt[nb][fc0+1][fr0]=vr0.y; Vt[nb][fc0+2][fr0]=vr0.z; Vt[nb][fc0+3][fr0]=vr0.w;
                Vt[nb][fc1+0][fr1]=vr1.x; Vt[nb][fc1+1][fr1]=vr1.y; Vt[nb][fc1+2][fr1]=vr1.z; Vt[nb][fc1+3][fr1]=vr1.w;
                if (lastk){
                    float4 t0 = qr0, t1 = qr1;
                    t0.x*=scale; t0.y*=scale; t0.z*=scale; t0.w*=scale;
                    t1.x*=scale; t1.y*=scale; t1.z*=scale; t1.w*=scale;
                    *(float4*)&Qs[fr0][fc0] = t0;
                    *(float4*)&Qs[fr1][fc1] = t1;
                }
            }
            __syncthreads();   // staged tile + Qs visible; Ps free for rewrite
        }
        // ---- stream this cam's UNNORMALIZED partial; snapshot running max ----
        #pragma unroll
        for (int i=0;i<4;i++){
            int qrow = q0 + ty*4 + i;
            if (qrow >= HWQ) continue;
            float2 a = unpack2(accA[i]);
            float2 v2 = unpack2(accB[i]);
            long rowoff = ((long)b*HWQ + qrow)*ND + cam*DIM + m*DH;
            ao[rowoff + tx]      = a.x + a.y;
            ao[rowoff + tx + 16] = v2.x + v2.y;
            if (tx == 0)
                fac[((long)(b*HWQ+qrow))*64 + cam*8 + m] = mrow[i];
        }
    }
    #pragma unroll
    for (int i=0;i<4;i++){
        int qrow = q0 + ty*4 + i;
        if (qrow >= HWQ || tx != 0) continue;
        long f0 = ((long)(b*HWQ+qrow))*64;
        fac[f0 + 48 + m] = mrow[i];
        fac[f0 + 56 + m] = lrow[i];
    }
}

// ---------------- layernorm over 1536 with deferred softmax normalization ----
__global__ void ln1536_kernel(const float* __restrict__ x, const float* __restrict__ fac,
                              const float* __restrict__ g, const float* __restrict__ b,
                              float* __restrict__ y){
    __shared__ float sh[8];
    __shared__ float bmu, brs;
    __shared__ float f48[48];
    long row = blockIdx.x;
    const float* p = x + row * (long)ND;
    const float* fr = fac + row * 64;
    int tid = threadIdx.x;
    if (tid < 48){
        int mm = tid & 7;
        f48[tid] = __expf(fr[tid] - fr[48+mm]) / fr[56+mm];
    }
    __syncthreads();
    float vals[6]; float s = 0.f;
    #pragma unroll
    for (int i=0;i<6;i++){
        int c = tid + i*256;
        float fv = f48[((c>>8)<<3) + ((c>>5)&7)];
        vals[i] = p[c] * fv; s += vals[i];
    }
    s = warpRedSum(s);
    if ((tid & 31) == 0) sh[tid>>5] = s;
    __syncthreads();
    if (tid == 0){ float t=0.f; for (int i=0;i<8;i++) t += sh[i]; bmu = t / (float)ND; }
    __syncthreads();
    float mu = bmu, vs = 0.f;
    #pragma unroll
    for (int i=0;i<6;i++){ float d = vals[i]-mu; vs += d*d; }
    vs = warpRedSum(vs);
    if ((tid & 31) == 0) sh[tid>>5] = vs;
    __syncthreads();
    if (tid == 0){ float t=0.f; for (int i=0;i<8;i++) t += sh[i]; brs = rsqrtf(t/(float)ND + 1e-5f); }
    __syncthreads();
    float rs = brs;
    float* q = y + row * (long)ND;
    #pragma unroll
    for (int i=0;i<6;i++){ int c = tid + i*256; q[c] = (vals[i]-mu)*rs*g[c] + b[c]; }
}

// ---------------- proj reduce ----------------
__global__ void reduce_proj_kernel(const float* __restrict__ p1, const float* __restrict__ p2,
                                   const float* __restrict__ baddq, const float* __restrict__ bproj,
                                   float* __restrict__ xb){
    long idx = (long)blockIdx.x * 256 + threadIdx.x;
    const long MN = (long)NB*HWQ*DIM;
    if (idx >= MN) return;
    int c = (int)(idx & 255);
    float v = bproj[c] + baddq[c];
    v += p1[idx] + p1[idx+MN] + p1[idx+2*MN];
    v += p2[idx] + p2[idx+MN] + p2[idx+2*MN];
    xb[idx] = v;
}

// ---------------- final ----------------
__global__ void final_kernel(const float* __restrict__ p3, const float* __restrict__ b2,
                             const float* __restrict__ x,
                             const float* __restrict__ g, const float* __restrict__ bb,
                             float* __restrict__ out){
    __shared__ float sh[8];
    __shared__ float bmu, brs;
    long row = blockIdx.x;
    const long MN = (long)NB*HWQ*DIM;
    int c = threadIdx.x;
    float v = p3[row*(long)DIM + c] + p3[MN + row*(long)DIM + c] + b2[c];
    float s = warpRedSum(v);
    if ((c & 31) == 0) sh[c>>5] = s;
    __syncthreads();
    if (c == 0){ float m=0.f; for (int i=0;i<8;i++) m += sh[i]; bmu = m / (float)DIM; }
    __syncthreads();
    float mu = bmu;
    float d = v - mu;
    float vs = warpRedSum(d*d);
    if ((c & 31) == 0) sh[c>>5] = vs;
    __syncthreads();
    if (c == 0){ float m=0.f; for (int i=0;i<8;i++) m += sh[i]; brs = rsqrtf(m/(float)DIM + 1e-5f); }
    __syncthreads();
    float y = d * brs * g[c] + bb[c] + x[row*(long)DIM + c];
    int b = (int)(row / HWQ), p = (int)(row % HWQ);
    out[((long)(b*DIM + c))*HWQ + p] = y;
}

// ---------------- host ----------------
static float* sym(const void* symbol){
    void* p = nullptr;
    cudaGetSymbolAddress(&p, symbol);
    return (float*)p;
}

static GemmP zeroP(){ GemmP p; memset(&p, 0, sizeof(p)); p.D1 = 1; p.SPLIT = 1; return p; }

static void launch_gemm(const GemmP& p, int batches){
    dim3 grid(p.N/64, (p.M+127)/128, batches * p.SPLIT);
    gemm_tc<<<grid, 128>>>(p);
}

extern "C" void kernel_launch(void* const* d_in, const int* in_sizes, int n_in,
                              void* d_out, int out_size){
    const float* q     = (const float*)d_in[0];
    const float* k     = (const float*)d_in[1];
    const float* v     = (const float*)d_in[2];
    const float* Wq    = (const float*)d_in[3];
    const float* bq    = (const float*)d_in[4];
    const float* Wk    = (const float*)d_in[5];
    const float* bk    = (const float*)d_in[6];
    const float* Wv    = (const float*)d_in[7];
    const float* bv    = (const float*)d_in[8];
    const float* Wproj = (const float*)d_in[9];
    const float* bproj = (const float*)d_in[10];
    const float* Waddq = (const float*)d_in[11];
    const float* baddq = (const float*)d_in[12];
    const float* W1    = (const float*)d_in[13];
    const float* b1    = (const float*)d_in[14];
    const float* W2    = (const float*)d_in[15];
    const float* b2    = (const float*)d_in[16];
    const float* g_pre = (const float*)d_in[17];
    const float* b_pre = (const float*)d_in[18];
    const float* g_nrm = (const float*)d_in[19];
    const float* b_nrm = (const float*)d_in[20];
    float* out = (float*)d_out;

    float* qT    = sym(g_qT);
    float* kpool = sym(g_kpool);
    float* vpool = sym(g_vpool);
    float* qf    = sym(g_qf);
    float* kf    = sym(g_kf);
    float* vf    = sym(g_vf);
    float* ao    = sym(g_attno);
    float* fac   = sym(g_fac);
    float* lnb   = sym(g_lnbuf);
    float* xb    = sym(g_xbuf);
    float* h1    = sym(g_h1);
    float* part1 = sym(g_part1);
    float* part2 = sym(g_part2);
    float* part3 = sym(g_part3);

    // 1) transpose q -> (b,p,nd)
    {
        dim3 grid((HWQ+31)/32, DIM/32, NB*NCAM);
        transpose_q_kernel<<<grid, dim3(32,8)>>>(q, qT);
    }
    // 2) pool k, v
    {
        long total = (long)NB*NCAM*DIM*PK;
        int blocks = (int)((total + 255) / 256);
        pool_kernel<<<blocks, 256>>>(k, kpool);
        pool_kernel<<<blocks, 256>>>(v, vpool);
    }
    // 3) add_q partials: qT @ Waddq, split-K x3
    {
        GemmP p = zeroP();
        p.A = qT; p.lda = ND; p.B = Waddq; p.ldb = DIM;
        p.C = part1; p.ldc = DIM; p.M = NB*HWQ; p.N = DIM;
        p.K = ND/3; p.SPLIT = 3; p.csplit = (long)NB*HWQ*DIM;
        launch_gemm(p, 1);
    }
    // 4) qf per (b,cam)
    {
        GemmP p = zeroP();
        p.A = qT; p.lda = ND; p.a0 = (long)HWQ*ND; p.a1 = DIM;
        p.B = Wq; p.ldb = DIM; p.bias = bq;
        p.C = qf; p.ldc = DIM; p.c0 = (long)NCAM*HWQ*DIM; p.c1 = (long)HWQ*DIM;
        p.M = HWQ; p.N = DIM; p.K = DIM; p.D1 = NCAM;
        launch_gemm(p, NB*NCAM);
    }
    // 5) kf, vf per (b,cam)
    {
        GemmP p = zeroP();
        p.A = kpool; p.lda = ND; p.a0 = (long)PK*ND; p.a1 = DIM;
        p.B = Wk; p.ldb = DIM; p.bias = bk;
        p.C = kf; p.ldc = DIM; p.c0 = (long)NCAM*PK*DIM; p.c1 = (long)PK*DIM;
        p.M = PK; p.N = DIM; p.K = DIM; p.D1 = NCAM;
        launch_gemm(p, NB*NCAM);
        p.A = vpool; p.B = Wv; p.bias = bv; p.C = vf;
        launch_gemm(p, NB*NCAM);
    }
    // 6) fused flash attention -> ao partials + fac
    {
        dim3 grid((HWQ+63)/64, NB*NHEAD);
        flash_kernel<<<grid, 256>>>(qf, kf, vf, ao, fac);
    }
    // 7) pre-layernorm (applies deferred softmax normalization)
    ln1536_kernel<<<NB*HWQ, 256>>>(ao, fac, g_pre, b_pre, lnb);
    // 8) proj partials: LN(out) @ Wproj, split-K x3
    {
        GemmP p = zeroP();
        p.A = lnb; p.lda = ND; p.B = Wproj; p.ldb = DIM;
        p.C = part2; p.ldc = DIM; p.M = NB*HWQ; p.N = DIM;
        p.K = ND/3; p.SPLIT = 3; p.csplit = (long)NB*HWQ*DIM;
        launch_gemm(p, 1);
    }
    // 8b) xb = sum(proj partials)+bproj + sum(addq partials)+baddq
    {
        long MN = (long)NB*HWQ*DIM;
        reduce_proj_kernel<<<(int)((MN+255)/256), 256>>>(part1, part2, baddq, bproj, xb);
    }
    // 9) h1 = gelu(x @ W1 + b1)
    {
        GemmP p = zeroP();
        p.A = xb; p.lda = DIM; p.B = W1; p.ldb = 2*DIM; p.bias = b1; p.gelu = 1;
        p.C = h1; p.ldc = 2*DIM; p.M = NB*HWQ; p.N = 2*DIM; p.K = DIM;
        launch_gemm(p, 1);
    }
    // 10) ffn2 partials: h1 @ W2, split-K x2
    {
        GemmP p = zeroP();
        p.A = h1; p.lda = 2*DIM; p.B = W2; p.ldb = DIM;
        p.C = part3; p.ldc = DIM; p.M = NB*HWQ; p.N = DIM;
        p.K = DIM; p.SPLIT = 2; p.csplit = (long)NB*HWQ*DIM;
        launch_gemm(p, 1);
    }
    // 11) out = transpose(x + LN(sum(part3)+b2))
    final_kernel<<<NB*HWQ, 256>>>(part3, b2, xb, g_nrm, b_nrm, out);
}

// round 7
// speedup vs baseline: 1.3416x; 1.0023x over previous
#include <cuda_runtime.h>
#include <math.h>
#include <string.h>

#define NB    2
#define NCAM  6
#define DIM   256
#define HWQ   2500
#define PK    625
#define NHEAD 8
#define DH    32
#define ND    1536

typedef unsigned long long u64;

// ---------------- f32x2 packed math (Blackwell) ----------------
__device__ __forceinline__ u64 ffma2(u64 a, u64 b, u64 c){
    u64 d; asm("fma.rn.f32x2 %0, %1, %2, %3;" : "=l"(d) : "l"(a), "l"(b), "l"(c)); return d;
}
__device__ __forceinline__ u64 fmul2(u64 a, u64 b){
    u64 d; asm("mul.rn.f32x2 %0, %1, %2;" : "=l"(d) : "l"(a), "l"(b)); return d;
}
__device__ __forceinline__ u64 pack2(float x, float y){
    u64 d; asm("mov.b64 %0, {%1, %2};" : "=l"(d) : "f"(x), "f"(y)); return d;
}
__device__ __forceinline__ float2 unpack2(u64 v){
    float2 r; asm("mov.b64 {%0, %1}, %2;" : "=f"(r.x), "=f"(r.y) : "l"(v)); return r;
}

// ---------------- scratch ----------------
__device__ float g_qT    [(long)NB*HWQ*ND];
__device__ float g_kpool [(long)NB*PK*ND];
__device__ float g_vpool [(long)NB*PK*ND];
__device__ float g_qf    [(long)NB*NCAM*HWQ*DIM];
__device__ float g_kf    [(long)NB*NCAM*PK*DIM];
__device__ float g_vf    [(long)NB*NCAM*PK*DIM];
__device__ float g_attno [(long)NB*HWQ*ND];
__device__ float g_fac   [(long)NB*HWQ*64];
__device__ float g_lnbuf [(long)NB*HWQ*ND];
__device__ float g_xbuf  [(long)NB*HWQ*DIM];
__device__ float g_h1    [(long)NB*HWQ*2*DIM];
__device__ float g_part1 [(long)3*NB*HWQ*DIM];
__device__ float g_part2 [(long)3*NB*HWQ*DIM];
__device__ float g_part3 [(long)2*NB*HWQ*DIM];

__device__ __forceinline__ float warpRedSum(float v){
    #pragma unroll
    for (int o=16;o;o>>=1) v += __shfl_xor_sync(0xffffffffu, v, o);
    return v;
}

// ---------------- transpose q: (b,cam,c,p) -> (b,p,cam*256+c) ----------------
__global__ void transpose_q_kernel(const float* __restrict__ q, float* __restrict__ qT){
    __shared__ float tile[32][33];
    int bn  = blockIdx.z;
    int b   = bn / NCAM, cam = bn % NCAM;
    int p0  = blockIdx.x * 32;
    int c0  = blockIdx.y * 32;
    int tx  = threadIdx.x, ty = threadIdx.y;
    #pragma unroll
    for (int i = ty; i < 32; i += 8){
        int c = c0 + i, p = p0 + tx;
        float v = 0.f;
        if (p < HWQ) v = q[((long)bn*DIM + c)*HWQ + p];
        tile[i][tx] = v;
    }
    __syncthreads();
    #pragma unroll
    for (int i = ty; i < 32; i += 8){
        int p = p0 + i, c = c0 + tx;
        if (p < HWQ)
            qT[((long)(b*HWQ + p))*ND + cam*DIM + c] = tile[tx][i];
    }
}

// ---------------- 2x2 pool + transpose ----------------
__global__ void pool_kernel(const float* __restrict__ src, float* __restrict__ dst){
    long idx = (long)blockIdx.x * blockDim.x + threadIdx.x;
    const long total = (long)NB*NCAM*DIM*PK;
    if (idx >= total) return;
    int kk  = (int)(idx % PK);  long t = idx / PK;
    int c   = (int)(t % DIM);   t /= DIM;
    int cam = (int)(t % NCAM);
    int b   = (int)(t / NCAM);
    int i = kk / 25, j = kk % 25;
    const float* p = src + ((long)((b*NCAM+cam)*DIM + c))*HWQ + (2*i)*50 + 2*j;
    float v = 0.25f * (p[0] + p[1] + p[50] + p[51]);
    dst[((long)(b*PK + kk)*NCAM + cam)*DIM + c] = v;
}

// ---------------- dense GEMM: 128 thr, BM128/BN64/BK16, 8x8/thread, split-K ----
struct GemmP {
    const float* A; const float* B; const float* bias; float* C;
    int lda, ldb, ldc;
    int M, N, K;            // K = per-split span
    int gelu, D1, SPLIT;
    long a0, a1, c0, c1, csplit;
};

__global__ __launch_bounds__(128,4) void gemm_tc(GemmP p){
    __shared__ float As[2][16][128];
    __shared__ float Bs[2][16][64];

    int z = blockIdx.z;
    int s = z % p.SPLIT; int zz = z / p.SPLIT;
    int i1 = zz % p.D1;  int i0 = zz / p.D1;
    const float* A = p.A + i0*p.a0 + i1*p.a1 + (long)s*p.K;
    const float* B = p.B + (long)s*p.K*p.ldb;
    float*       C = p.C + i0*p.c0 + i1*p.c1 + (long)s*p.csplit;

    int tid = threadIdx.x;
    int tx = tid & 7, ty = tid >> 3;
    int row0 = blockIdx.y*128, col0 = blockIdx.x*64;

    int arow = row0 + tid;
    int brow = tid >> 3;
    int bc0  = (tid & 7) * 2;
    int pb0  = (bc0 ^ (bc0 >> 3)) * 4;
    int pb1  = ((bc0+1) ^ ((bc0+1) >> 3)) * 4;

    u64 acc[8][4];
    #pragma unroll
    for (int i=0;i<8;i++)
        #pragma unroll
        for (int j=0;j<4;j++) acc[i][j] = 0ULL;

    const float4 z4 = make_float4(0.f,0.f,0.f,0.f);
    float4 ra[4], rb0, rb1;

    int nt = p.K / 16;
    if (arow < p.M){
        const float* pa = A + (long)arow*p.lda;
        ra[0]=*(const float4*)pa; ra[1]=*(const float4*)(pa+4);
        ra[2]=*(const float4*)(pa+8); ra[3]=*(const float4*)(pa+12);
    } else { ra[0]=z4; ra[1]=z4; ra[2]=z4; ra[3]=z4; }
    {
        const float* pb = B + (long)brow*p.ldb + col0 + bc0*4;
        rb0 = *(const float4*)pb; rb1 = *(const float4*)(pb+4);
    }
    {
        #pragma unroll
        for (int j=0;j<4;j++){
            As[0][j*4+0][tid]=ra[j].x; As[0][j*4+1][tid]=ra[j].y;
            As[0][j*4+2][tid]=ra[j].z; As[0][j*4+3][tid]=ra[j].w;
        }
        *(float4*)&Bs[0][brow][pb0] = rb0;
        *(float4*)&Bs[0][brow][pb1] = rb1;
    }
    __syncthreads();
    int cur = 0;
    for (int t=0; t<nt; t++){
        if (t+1 < nt){
            int k0 = (t+1)*16;
            if (arow < p.M){
                const float* pa = A + (long)arow*p.lda + k0;
                ra[0]=*(const float4*)pa; ra[1]=*(const float4*)(pa+4);
                ra[2]=*(const float4*)(pa+8); ra[3]=*(const float4*)(pa+12);
            } else { ra[0]=z4; ra[1]=z4; ra[2]=z4; ra[3]=z4; }
            const float* pb = B + (long)(k0+brow)*p.ldb + col0 + bc0*4;
            rb0 = *(const float4*)pb; rb1 = *(const float4*)(pb+4);
        }
        #pragma unroll
        for (int kk=0; kk<16; kk++){
            float4 a0 = *(const float4*)&As[cur][kk][ty*8];
            float4 a1 = *(const float4*)&As[cur][kk][ty*8+4];
            ulonglong2 b0 = *(const ulonglong2*)&Bs[cur][kk][pb0];
            ulonglong2 b1 = *(const ulonglong2*)&Bs[cur][kk][pb1];
            u64 ap;
            ap=pack2(a0.x,a0.x); acc[0][0]=ffma2(ap,b0.x,acc[0][0]); acc[0][1]=ffma2(ap,b0.y,acc[0][1]); acc[0][2]=ffma2(ap,b1.x,acc[0][2]); acc[0][3]=ffma2(ap,b1.y,acc[0][3]);
            ap=pack2(a0.y,a0.y); acc[1][0]=ffma2(ap,b0.x,acc[1][0]); acc[1][1]=ffma2(ap,b0.y,acc[1][1]); acc[1][2]=ffma2(ap,b1.x,acc[1][2]); acc[1][3]=ffma2(ap,b1.y,acc[1][3]);
            ap=pack2(a0.z,a0.z); acc[2][0]=ffma2(ap,b0.x,acc[2][0]); acc[2][1]=ffma2(ap,b0.y,acc[2][1]); acc[2][2]=ffma2(ap,b1.x,acc[2][2]); acc[2][3]=ffma2(ap,b1.y,acc[2][3]);
            ap=pack2(a0.w,a0.w); acc[3][0]=ffma2(ap,b0.x,acc[3][0]); acc[3][1]=ffma2(ap,b0.y,acc[3][1]); acc[3][2]=ffma2(ap,b1.x,acc[3][2]); acc[3][3]=ffma2(ap,b1.y,acc[3][3]);
            ap=pack2(a1.x,a1.x); acc[4][0]=ffma2(ap,b0.x,acc[4][0]); acc[4][1]=ffma2(ap,b0.y,acc[4][1]); acc[4][2]=ffma2(ap,b1.x,acc[4][2]); acc[4][3]=ffma2(ap,b1.y,acc[4][3]);
            ap=pack2(a1.y,a1.y); acc[5][0]=ffma2(ap,b0.x,acc[5][0]); acc[5][1]=ffma2(ap,b0.y,acc[5][1]); acc[5][2]=ffma2(ap,b1.x,acc[5][2]); acc[5][3]=ffma2(ap,b1.y,acc[5][3]);
            ap=pack2(a1.z,a1.z); acc[6][0]=ffma2(ap,b0.x,acc[6][0]); acc[6][1]=ffma2(ap,b0.y,acc[6][1]); acc[6][2]=ffma2(ap,b1.x,acc[6][2]); acc[6][3]=ffma2(ap,b1.y,acc[6][3]);
            ap=pack2(a1.w,a1.w); acc[7][0]=ffma2(ap,b0.x,acc[7][0]); acc[7][1]=ffma2(ap,b0.y,acc[7][1]); acc[7][2]=ffma2(ap,b1.x,acc[7][2]); acc[7][3]=ffma2(ap,b1.y,acc[7][3]);
        }
        if (t+1 < nt){
            int nb = cur ^ 1;
            #pragma unroll
            for (int j=0;j<4;j++){
                As[nb][j*4+0][tid]=ra[j].x; As[nb][j*4+1][tid]=ra[j].y;
                As[nb][j*4+2][tid]=ra[j].z; As[nb][j*4+3][tid]=ra[j].w;
            }
            *(float4*)&Bs[nb][brow][pb0] = rb0;
            *(float4*)&Bs[nb][brow][pb1] = rb1;
            __syncthreads();
            cur = nb;
        }
    }
    int colb = col0 + tx*8;
    float4 bia0, bia1;
    if (p.SPLIT == 1 && p.bias){
        bia0 = *(const float4*)(p.bias + colb);
        bia1 = *(const float4*)(p.bias + colb + 4);
    } else { bia0 = z4; bia1 = z4; }
    #pragma unroll
    for (int i=0;i<8;i++){
        int r = row0 + ty*8 + i;
        if (r >= p.M) continue;
        float2 v0 = unpack2(acc[i][0]), v1 = unpack2(acc[i][1]);
        float2 v2 = unpack2(acc[i][2]), v3 = unpack2(acc[i][3]);
        float4 o0 = make_float4(v0.x+bia0.x, v0.y+bia0.y, v1.x+bia0.z, v1.y+bia0.w);
        float4 o1 = make_float4(v2.x+bia1.x, v2.y+bia1.y, v3.x+bia1.z, v3.y+bia1.w);
        if (p.gelu){
            o0.x*=normcdff(o0.x); o0.y*=normcdff(o0.y); o0.z*=normcdff(o0.z); o0.w*=normcdff(o0.w);
            o1.x*=normcdff(o1.x); o1.y*=normcdff(o1.y); o1.z*=normcdff(o1.z); o1.w*=normcdff(o1.w);
        }
        *(float4*)(C + (long)r*p.ldc + colb)     = o0;
        *(float4*)(C + (long)r*p.ldc + colb + 4) = o1;
    }
}

// ---------------- fused flash attention: pipelined K/V, deferred normalization ----
__global__ __launch_bounds__(256,2) void flash_kernel(
    const float* __restrict__ qf, const float* __restrict__ kf,
    const float* __restrict__ vf, float* __restrict__ ao, float* __restrict__ fac)
{
    __shared__ float Qs[64][32];
    __shared__ float Ks[2][64][36];
    __shared__ float Vt[2][32][68];
    __shared__ float Ps[64][68];

    int zz = blockIdx.y; int b = zz >> 3, m = zz & 7;
    int q0 = blockIdx.x * 64;
    int tid = threadIdx.x, tx = tid & 15, ty = tid >> 4;
    const float scale = 0.17677669529663689f;
    const float4 z4 = make_float4(0.f,0.f,0.f,0.f);

    // per-thread fill coordinates (2 chunks of 256 threads cover 64 rows x 32 cols)
    int fr0 = tid >> 3,        fc0 = (tid & 7) * 4;          // chunk 0
    int fr1 = (tid + 256) >> 3, fc1 = fc0;                   // chunk 1
    bool qv0 = (q0 + fr0) < HWQ, qv1 = (q0 + fr1) < HWQ;

    const float* qb0 = qf + ((long)(b*NCAM)*HWQ)*DIM + m*DH;   // cam stride HWQ*DIM
    const float* kb0 = kf + ((long)(b*NCAM)*PK)*DIM + m*DH;
    const float* vb0 = vf + ((long)(b*NCAM)*PK)*DIM + m*DH;
    const long QCAM = (long)HWQ*DIM, KCAM = (long)PK*DIM;

    float mrow[4] = {-1e30f,-1e30f,-1e30f,-1e30f};
    float lrow[4] = {0.f,0.f,0.f,0.f};

    float4 qr0, qr1, kr0, kr1, vr0, vr1;

    // initial prefetch: Q(cam0) + K/V(cam0, tile0)
    {
        qr0 = qv0 ? *(const float4*)(qb0 + (long)(q0+fr0)*DIM + fc0) : z4;
        qr1 = qv1 ? *(const float4*)(qb0 + (long)(q0+fr1)*DIM + fc1) : z4;
        kr0 = *(const float4*)(kb0 + (long)fr0*DIM + fc0);
        vr0 = *(const float4*)(vb0 + (long)fr0*DIM + fc0);
        kr1 = *(const float4*)(kb0 + (long)fr1*DIM + fc1);
        vr1 = *(const float4*)(vb0 + (long)fr1*DIM + fc1);
    }
    // stage
    {
        qr0.x*=scale; qr0.y*=scale; qr0.z*=scale; qr0.w*=scale;
        qr1.x*=scale; qr1.y*=scale; qr1.z*=scale; qr1.w*=scale;
        *(float4*)&Qs[fr0][fc0] = qr0;
        *(float4*)&Qs[fr1][fc1] = qr1;
        *(float4*)&Ks[0][fr0][fc0] = kr0;
        *(float4*)&Ks[0][fr1][fc1] = kr1;
        Vt[0][fc0+0][fr0]=vr0.x; Vt[0][fc0+1][fr0]=vr0.y; Vt[0][fc0+2][fr0]=vr0.z; Vt[0][fc0+3][fr0]=vr0.w;
        Vt[0][fc1+0][fr1]=vr1.x; Vt[0][fc1+1][fr1]=vr1.y; Vt[0][fc1+2][fr1]=vr1.z; Vt[0][fc1+3][fr1]=vr1.w;
    }
    __syncthreads();

    for (int cam=0; cam<6; cam++){
        u64 accA[4], accB[4];
        #pragma unroll
        for (int i=0;i<4;i++){ accA[i]=0ULL; accB[i]=0ULL; }

        for (int kt=0; kt<10; kt++){
            int cur = kt & 1;
            bool lastk = (kt == 9);
            bool havePf = (!lastk) || (cam < 5);
            // ---- prefetch next tile (regs only) ----
            if (!lastk){
                int kk0 = (kt+1)*64;
                const float* kb = kb0 + cam*KCAM;
                const float* vb = vb0 + cam*KCAM;
                bool v0ok = (kk0 + fr0) < PK, v1ok = (kk0 + fr1) < PK;
                kr0 = v0ok ? *(const float4*)(kb + (long)(kk0+fr0)*DIM + fc0) : z4;
                vr0 = v0ok ? *(const float4*)(vb + (long)(kk0+fr0)*DIM + fc0) : z4;
                kr1 = v1ok ? *(const float4*)(kb + (long)(kk0+fr1)*DIM + fc1) : z4;
                vr1 = v1ok ? *(const float4*)(vb + (long)(kk0+fr1)*DIM + fc1) : z4;
            } else if (cam < 5){
                const float* kb = kb0 + (cam+1)*KCAM;
                const float* vb = vb0 + (cam+1)*KCAM;
                const float* qb = qb0 + (cam+1)*QCAM;
                kr0 = *(const float4*)(kb + (long)fr0*DIM + fc0);
                vr0 = *(const float4*)(vb + (long)fr0*DIM + fc0);
                kr1 = *(const float4*)(kb + (long)fr1*DIM + fc1);
                vr1 = *(const float4*)(vb + (long)fr1*DIM + fc1);
                qr0 = qv0 ? *(const float4*)(qb + (long)(q0+fr0)*DIM + fc0) : z4;
                qr1 = qv1 ? *(const float4*)(qb + (long)(q0+fr1)*DIM + fc1) : z4;
            }

            // ---- QK on buffer cur ----
            int kk0 = kt*64;
            u64 sacc[4][4];
            #pragma unroll
            for (int i=0;i<4;i++)
                #pragma unroll
                for (int j=0;j<4;j++) sacc[i][j]=0ULL;
            #pragma unroll
            for (int c4=0;c4<8;c4++){
                ulonglong2 qv[4], kv[4];
                #pragma unroll
                for (int i=0;i<4;i++) qv[i] = *(const ulonglong2*)&Qs[ty*4+i][c4*4];
                #pragma unroll
                for (int j=0;j<4;j++) kv[j] = *(const ulonglong2*)&Ks[cur][tx+16*j][c4*4];
                #pragma unroll
                for (int i=0;i<4;i++)
                    #pragma unroll
                    for (int j=0;j<4;j++){
                        sacc[i][j]=ffma2(qv[i].x,kv[j].x,sacc[i][j]);
                        sacc[i][j]=ffma2(qv[i].y,kv[j].y,sacc[i][j]);
                    }
            }
            // ---- online softmax ----
            #pragma unroll
            for (int i=0;i<4;i++){
                float s_[4];
                float tmax = -1e30f;
                #pragma unroll
                for (int j=0;j<4;j++){
                    float2 t2 = unpack2(sacc[i][j]);
                    float s = t2.x + t2.y;
                    if (kk0 + tx + 16*j >= PK) s = -1e30f;
                    s_[j] = s; tmax = fmaxf(tmax, s);
                }
                #pragma unroll
                for (int off=1; off<16; off<<=1)
                    tmax = fmaxf(tmax, __shfl_xor_sync(0xffffffffu, tmax, off));
                float mnew = fmaxf(mrow[i], tmax);
                float corr = __expf(mrow[i] - mnew);
                float rsum = 0.f;
                #pragma unroll
                for (int j=0;j<4;j++){
                    float pv = __expf(s_[j] - mnew);
                    rsum += pv;
                    Ps[ty*4+i][tx+16*j] = pv;
                }
                #pragma unroll
                for (int off=1; off<16; off<<=1)
                    rsum += __shfl_xor_sync(0xffffffffu, rsum, off);
                lrow[i] = lrow[i]*corr + rsum;
                mrow[i] = mnew;
                u64 cp = pack2(corr, corr);
                accA[i] = fmul2(accA[i], cp);
                accB[i] = fmul2(accB[i], cp);
            }
            __syncthreads();   // Ps visible; all warps past QK(kt)

            // ---- PV on buffer cur ----
            #pragma unroll
            for (int k4=0;k4<16;k4++){
                ulonglong2 va = *(const ulonglong2*)&Vt[cur][tx][k4*4];
                ulonglong2 vb = *(const ulonglong2*)&Vt[cur][tx+16][k4*4];
                #pragma unroll
                for (int i=0;i<4;i++){
                    ulonglong2 pp = *(const ulonglong2*)&Ps[ty*4+i][k4*4];
                    accA[i]=ffma2(pp.x,va.x,accA[i]); accA[i]=ffma2(pp.y,va.y,accA[i]);
                    accB[i]=ffma2(pp.x,vb.x,accB[i]); accB[i]=ffma2(pp.y,vb.y,accB[i]);
                }
            }

            // ---- stage prefetched tile into buffer cur^1 ----
            if (havePf){
                int nb = cur ^ 1;
                *(float4*)&Ks[nb][fr0][fc0] = kr0;
                *(float4*)&Ks[nb][fr1][fc1] = kr1;
                Vt[nb][fc0+0][fr0]=vr0.x; Vt[nb][fc0+1][fr0]=vr0.y; Vt[nb][fc0+2][fr0]=vr0.z; Vt[nb][fc0+3][fr0]=vr0.w;
                Vt[nb][fc1+0][fr1]=vr1.x; Vt[nb][fc1+1][fr1]=vr1.y; Vt[nb][fc1+2][fr1]=vr1.z; Vt[nb][fc1+3][fr1]=vr1.w;
                if (lastk){
                    float4 t0 = qr0, t1 = qr1;
                    t0.x*=scale; t0.y*=scale; t0.z*=scale; t0.w*=scale;
                    t1.x*=scale; t1.y*=scale; t1.z*=scale; t1.w*=scale;
                    *(float4*)&Qs[fr0][fc0] = t0;
                    *(float4*)&Qs[fr1][fc1] = t1;
                }
            }
            __syncthreads();   // staged tile + Qs visible; Ps free for rewrite
        }
        // ---- stream this cam's UNNORMALIZED partial; snapshot running max ----
        #pragma unroll
        for (int i=0;i<4;i++){
            int qrow = q0 + ty*4 + i;
            if (qrow >= HWQ) continue;
            float2 a = unpack2(accA[i]);
            float2 v2 = unpack2(accB[i]);
            long rowoff = ((long)b*HWQ + qrow)*ND + cam*DIM + m*DH;
            ao[rowoff + tx]      = a.x + a.y;
            ao[rowoff + tx + 16] = v2.x + v2.y;
            if (tx == 0)
                fac[((long)(b*HWQ+qrow))*64 + cam*8 + m] = mrow[i];
        }
    }
    #pragma unroll
    for (int i=0;i<4;i++){
        int qrow = q0 + ty*4 + i;
        if (qrow >= HWQ || tx != 0) continue;
        long f0 = ((long)(b*HWQ+qrow))*64;
        fac[f0 + 48 + m] = mrow[i];
        fac[f0 + 56 + m] = lrow[i];
    }
}

// ---------------- layernorm over 1536 with deferred softmax normalization ----
__global__ void ln1536_kernel(const float* __restrict__ x, const float* __restrict__ fac,
                              const float* __restrict__ g, const float* __restrict__ b,
                              float* __restrict__ y){
    __shared__ float sh[8];
    __shared__ float bmu, brs;
    __shared__ float f48[48];
    long row = blockIdx.x;
    const float* p = x + row * (long)ND;
    const float* fr = fac + row * 64;
    int tid = threadIdx.x;
    if (tid < 48){
        int mm = tid & 7;
        f48[tid] = __expf(fr[tid] - fr[48+mm]) / fr[56+mm];
    }
    __syncthreads();
    float vals[6]; float s = 0.f;
    #pragma unroll
    for (int i=0;i<6;i++){
        int c = tid + i*256;
        float fv = f48[((c>>8)<<3) + ((c>>5)&7)];
        vals[i] = p[c] * fv; s += vals[i];
    }
    s = warpRedSum(s);
    if ((tid & 31) == 0) sh[tid>>5] = s;
    __syncthreads();
    if (tid == 0){ float t=0.f; for (int i=0;i<8;i++) t += sh[i]; bmu = t / (float)ND; }
    __syncthreads();
    float mu = bmu, vs = 0.f;
    #pragma unroll
    for (int i=0;i<6;i++){ float d = vals[i]-mu; vs += d*d; }
    vs = warpRedSum(vs);
    if ((tid & 31) == 0) sh[tid>>5] = vs;
    __syncthreads();
    if (tid == 0){ float t=0.f; for (int i=0;i<8;i++) t += sh[i]; brs = rsqrtf(t/(float)ND + 1e-5f); }
    __syncthreads();
    float rs = brs;
    float* q = y + row * (long)ND;
    #pragma unroll
    for (int i=0;i<6;i++){ int c = tid + i*256; q[c] = (vals[i]-mu)*rs*g[c] + b[c]; }
}

// ---------------- proj reduce ----------------
__global__ void reduce_proj_kernel(const float* __restrict__ p1, const float* __restrict__ p2,
                                   const float* __restrict__ baddq, const float* __restrict__ bproj,
                                   float* __restrict__ xb){
    long idx = (long)blockIdx.x * 256 + threadIdx.x;
    const long MN = (long)NB*HWQ*DIM;
    if (idx >= MN) return;
    int c = (int)(idx & 255);
    float v = bproj[c] + baddq[c];
    v += p1[idx] + p1[idx+MN] + p1[idx+2*MN];
    v += p2[idx] + p2[idx+MN] + p2[idx+2*MN];
    xb[idx] = v;
}

// ---------------- final ----------------
__global__ void final_kernel(const float* __restrict__ p3, const float* __restrict__ b2,
                             const float* __restrict__ x,
                             const float* __restrict__ g, const float* __restrict__ bb,
                             float* __restrict__ out){
    __shared__ float sh[8];
    __shared__ float bmu, brs;
    long row = blockIdx.x;
    const long MN = (long)NB*HWQ*DIM;
    int c = threadIdx.x;
    float v = p3[row*(long)DIM + c] + p3[MN + row*(long)DIM + c] + b2[c];
    float s = warpRedSum(v);
    if ((c & 31) == 0) sh[c>>5] = s;
    __syncthreads();
    if (c == 0){ float m=0.f; for (int i=0;i<8;i++) m += sh[i]; bmu = m / (float)DIM; }
    __syncthreads();
    float mu = bmu;
    float d = v - mu;
    float vs = warpRedSum(d*d);
    if ((c & 31) == 0) sh[c>>5] = vs;
    __syncthreads();
    if (c == 0){ float m=0.f; for (int i=0;i<8;i++) m += sh[i]; brs = rsqrtf(m/(float)DIM + 1e-5f); }
    __syncthreads();
    float y = d * brs * g[c] + bb[c] + x[row*(long)DIM + c];
    int b = (int)(row / HWQ), p = (int)(row % HWQ);
    out[((long)(b*DIM + c))*HWQ + p] = y;
}

// ---------------- host ----------------
static float* sym(const void* symbol){
    void* p = nullptr;
    cudaGetSymbolAddress(&p, symbol);
    return (float*)p;
}

static GemmP zeroP(){ GemmP p; memset(&p, 0, sizeof(p)); p.D1 = 1; p.SPLIT = 1; return p; }

static void launch_gemm(const GemmP& p, int batches){
    dim3 grid(p.N/64, (p.M+127)/128, batches * p.SPLIT);
    gemm_tc<<<grid, 128>>>(p);
}

extern "C" void kernel_launch(void* const* d_in, const int* in_sizes, int n_in,
                              void* d_out, int out_size){
    const float* q     = (const float*)d_in[0];
    const float* k     = (const float*)d_in[1];
    const float* v     = (const float*)d_in[2];
    const float* Wq    = (const float*)d_in[3];
    const float* bq    = (const float*)d_in[4];
    const float* Wk    = (const float*)d_in[5];
    const float* bk    = (const float*)d_in[6];
    const float* Wv    = (const float*)d_in[7];
    const float* bv    = (const float*)d_in[8];
    const float* Wproj = (const float*)d_in[9];
    const float* bproj = (const float*)d_in[10];
    const float* Waddq = (const float*)d_in[11];
    const float* baddq = (const float*)d_in[12];
    const float* W1    = (const float*)d_in[13];
    const float* b1    = (const float*)d_in[14];
    const float* W2    = (const float*)d_in[15];
    const float* b2    = (const float*)d_in[16];
    const float* g_pre = (const float*)d_in[17];
    const float* b_pre = (const float*)d_in[18];
    const float* g_nrm = (const float*)d_in[19];
    const float* b_nrm = (const float*)d_in[20];
    float* out = (float*)d_out;

    float* qT    = sym(g_qT);
    float* kpool = sym(g_kpool);
    float* vpool = sym(g_vpool);
    float* qf    = sym(g_qf);
    float* kf    = sym(g_kf);
    float* vf    = sym(g_vf);
    float* ao    = sym(g_attno);
    float* fac   = sym(g_fac);
    float* lnb   = sym(g_lnbuf);
    float* xb    = sym(g_xbuf);
    float* h1    = sym(g_h1);
    float* part1 = sym(g_part1);
    float* part2 = sym(g_part2);
    float* part3 = sym(g_part3);

    // 1) transpose q -> (b,p,nd)
    {
        dim3 grid((HWQ+31)/32, DIM/32, NB*NCAM);
        transpose_q_kernel<<<grid, dim3(32,8)>>>(q, qT);
    }
    // 2) pool k, v
    {
        long total = (long)NB*NCAM*DIM*PK;
        int blocks = (int)((total + 255) / 256);
        pool_kernel<<<blocks, 256>>>(k, kpool);
        pool_kernel<<<blocks, 256>>>(v, vpool);
    }
    // 3) add_q partials: qT @ Waddq, split-K x3
    {
        GemmP p = zeroP();
        p.A = qT; p.lda = ND; p.B = Waddq; p.ldb = DIM;
        p.C = part1; p.ldc = DIM; p.M = NB*HWQ; p.N = DIM;
        p.K = ND/3; p.SPLIT = 3; p.csplit = (long)NB*HWQ*DIM;
        launch_gemm(p, 1);
    }
    // 4) qf per (b,cam)
    {
        GemmP p = zeroP();
        p.A = qT; p.lda = ND; p.a0 = (long)HWQ*ND; p.a1 = DIM;
        p.B = Wq; p.ldb = DIM; p.bias = bq;
        p.C = qf; p.ldc = DIM; p.c0 = (long)NCAM*HWQ*DIM; p.c1 = (long)HWQ*DIM;
        p.M = HWQ; p.N = DIM; p.K = DIM; p.D1 = NCAM;
        launch_gemm(p, NB*NCAM);
    }
    // 5) kf, vf per (b,cam)
    {
        GemmP p = zeroP();
        p.A = kpool; p.lda = ND; p.a0 = (long)PK*ND; p.a1 = DIM;
        p.B = Wk; p.ldb = DIM; p.bias = bk;
        p.C = kf; p.ldc = DIM; p.c0 = (long)NCAM*PK*DIM; p.c1 = (long)PK*DIM;
        p.M = PK; p.N = DIM; p.K = DIM; p.D1 = NCAM;
        launch_gemm(p, NB*NCAM);
        p.A = vpool; p.B = Wv; p.bias = bv; p.C = vf;
        launch_gemm(p, NB*NCAM);
    }
    // 6) fused flash attention -> ao partials + fac
    {
        dim3 grid((HWQ+63)/64, NB*NHEAD);
        flash_kernel<<<grid, 256>>>(qf, kf, vf, ao, fac);
    }
    // 7) pre-layernorm (applies deferred softmax normalization)
    ln1536_kernel<<<NB*HWQ, 256>>>(ao, fac, g_pre, b_pre, lnb);
    // 8) proj partials: LN(out) @ Wproj, split-K x3
    {
        GemmP p = zeroP();
        p.A = lnb; p.lda = ND; p.B = Wproj; p.ldb = DIM;
        p.C = part2; p.ldc = DIM; p.M = NB*HWQ; p.N = DIM;
        p.K = ND/3; p.SPLIT = 3; p.csplit = (long)NB*HWQ*DIM;
        launch_gemm(p, 1);
    }
    // 8b) xb = sum(proj partials)+bproj + sum(addq partials)+baddq
    {
        long MN = (long)NB*HWQ*DIM;
        reduce_proj_kernel<<<(int)((MN+255)/256), 256>>>(part1, part2, baddq, bproj, xb);
    }
    // 9) h1 = gelu(x @ W1 + b1)
    {
        GemmP p = zeroP();
        p.A = xb; p.lda = DIM; p.B = W1; p.ldb = 2*DIM; p.bias = b1; p.gelu = 1;
        p.C = h1; p.ldc = 2*DIM; p.M = NB*HWQ; p.N = 2*DIM; p.K = DIM;
        launch_gemm(p, 1);
    }
    // 10) ffn2 partials: h1 @ W2, split-K x2
    {
        GemmP p = zeroP();
        p.A = h1; p.lda = 2*DIM; p.B = W2; p.ldb = DIM;
        p.C = part3; p.ldc = DIM; p.M = NB*HWQ; p.N = DIM;
        p.K = DIM; p.SPLIT = 2; p.csplit = (long)NB*HWQ*DIM;
        launch_gemm(p, 1);
    }
    // 11) out = transpose(x + LN(sum(part3)+b2))
    final_kernel<<<NB*HWQ, 256>>>(part3, b2, xb, g_nrm, b_nrm, out);
}

// round 9
// speedup vs baseline: 1.5674x; 1.1683x over previous
#include <cuda_runtime.h>
#include <math.h>
#include <string.h>

#define NB    2
#define NCAM  6
#define DIM   256
#define HWQ   2500
#define PK    625
#define NHEAD 8
#define DH    32
#define ND    1536

typedef unsigned long long u64;

__device__ __forceinline__ u64 ffma2(u64 a, u64 b, u64 c){
    u64 d; asm("fma.rn.f32x2 %0, %1, %2, %3;" : "=l"(d) : "l"(a), "l"(b), "l"(c)); return d;
}
__device__ __forceinline__ u64 fmul2(u64 a, u64 b){
    u64 d; asm("mul.rn.f32x2 %0, %1, %2;" : "=l"(d) : "l"(a), "l"(b)); return d;
}
__device__ __forceinline__ u64 pack2(float x, float y){
    u64 d; asm("mov.b64 %0, {%1, %2};" : "=l"(d) : "f"(x), "f"(y)); return d;
}
__device__ __forceinline__ float2 unpack2(u64 v){
    float2 r; asm("mov.b64 {%0, %1}, %2;" : "=f"(r.x), "=f"(r.y) : "l"(v)); return r;
}

__device__ float g_qT    [(long)NB*HWQ*ND];
__device__ float g_kpool [(long)NB*PK*ND];
__device__ float g_vpool [(long)NB*PK*ND];
__device__ float g_qf    [(long)NB*NCAM*HWQ*DIM];
__device__ float g_kf    [(long)NB*NCAM*PK*DIM];
__device__ float g_vf    [(long)NB*NCAM*PK*DIM];
__device__ float g_attno [(long)NB*HWQ*ND];
__device__ float g_fac   [(long)NB*HWQ*96];
__device__ float g_lnbuf [(long)NB*HWQ*ND];
__device__ float g_xbuf  [(long)NB*HWQ*DIM];
__device__ float g_h1    [(long)NB*HWQ*2*DIM];
__device__ float g_part1 [(long)3*NB*HWQ*DIM];
__device__ float g_part2 [(long)3*NB*HWQ*DIM];
__device__ float g_part3 [(long)2*NB*HWQ*DIM];

__device__ __forceinline__ float warpRedSum(float v){
    #pragma unroll
    for (int o=16;o;o>>=1) v += __shfl_xor_sync(0xffffffffu, v, o);
    return v;
}

__global__ void transpose_q_kernel(const float* __restrict__ q, float* __restrict__ qT){
    __shared__ float tile[32][33];
    int bn  = blockIdx.z;
    int b   = bn / NCAM, cam = bn % NCAM;
    int p0  = blockIdx.x * 32;
    int c0  = blockIdx.y * 32;
    int tx  = threadIdx.x, ty = threadIdx.y;
    #pragma unroll
    for (int i = ty; i < 32; i += 8){
        int c = c0 + i, p = p0 + tx;
        float v = 0.f;
        if (p < HWQ) v = q[((long)bn*DIM + c)*HWQ + p];
        tile[i][tx] = v;
    }
    __syncthreads();
    #pragma unroll
    for (int i = ty; i < 32; i += 8){
        int p = p0 + i, c = c0 + tx;
        if (p < HWQ)
            qT[((long)(b*HWQ + p))*ND + cam*DIM + c] = tile[tx][i];
    }
}

__global__ void pool_kernel(const float* __restrict__ src, float* __restrict__ dst){
    long idx = (long)blockIdx.x * blockDim.x + threadIdx.x;
    const long total = (long)NB*NCAM*DIM*PK;
    if (idx >= total) return;
    int kk  = (int)(idx % PK);  long t = idx / PK;
    int c   = (int)(t % DIM);   t /= DIM;
    int cam = (int)(t % NCAM);
    int b   = (int)(t / NCAM);
    int i = kk / 25, j = kk % 25;
    const float* p = src + ((long)((b*NCAM+cam)*DIM + c))*HWQ + (2*i)*50 + 2*j;
    float v = 0.25f * (p[0] + p[1] + p[50] + p[51]);
    dst[((long)(b*PK + kk)*NCAM + cam)*DIM + c] = v;
}

struct GemmP {
    const float* A; const float* B; const float* bias; float* C;
    int lda, ldb, ldc;
    int M, N, K;
    int gelu, D1, SPLIT;
    long a0, a1, c0, c1, csplit;
};

__global__ __launch_bounds__(128,4) void gemm_tc(GemmP p){
    __shared__ float As[2][16][128];
    __shared__ float Bs[2][16][64];

    int z = blockIdx.z;
    int s = z % p.SPLIT; int zz = z / p.SPLIT;
    int i1 = zz % p.D1;  int i0 = zz / p.D1;
    const float* A = p.A + i0*p.a0 + i1*p.a1 + (long)s*p.K;
    const float* B = p.B + (long)s*p.K*p.ldb;
    float*       C = p.C + i0*p.c0 + i1*p.c1 + (long)s*p.csplit;

    int tid = threadIdx.x;
    int tx = tid & 7, ty = tid >> 3;
    int row0 = blockIdx.y*128, col0 = blockIdx.x*64;

    int arow = row0 + tid;
    int brow = tid >> 3;
    int bc0  = (tid & 7) * 2;
    int pb0  = (bc0 ^ (bc0 >> 3)) * 4;
    int pb1  = ((bc0+1) ^ ((bc0+1) >> 3)) * 4;

    u64 acc[8][4];
    #pragma unroll
    for (int i=0;i<8;i++)
        #pragma unroll
        for (int j=0;j<4;j++) acc[i][j] = 0ULL;

    const float4 z4 = make_float4(0.f,0.f,0.f,0.f);
    float4 ra[4], rb0, rb1;

    int nt = p.K / 16;
    if (arow < p.M){
        const float* pa = A + (long)arow*p.lda;
        ra[0]=*(const float4*)pa; ra[1]=*(const float4*)(pa+4);
        ra[2]=*(const float4*)(pa+8); ra[3]=*(const float4*)(pa+12);
    } else { ra[0]=z4; ra[1]=z4; ra[2]=z4; ra[3]=z4; }
    {
        const float* pb = B + (long)brow*p.ldb + col0 + bc0*4;
        rb0 = *(const float4*)pb; rb1 = *(const float4*)(pb+4);
    }
    {
        #pragma unroll
        for (int j=0;j<4;j++){
            As[0][j*4+0][tid]=ra[j].x; As[0][j*4+1][tid]=ra[j].y;
            As[0][j*4+2][tid]=ra[j].z; As[0][j*4+3][tid]=ra[j].w;
        }
        *(float4*)&Bs[0][brow][pb0] = rb0;
        *(float4*)&Bs[0][brow][pb1] = rb1;
    }
    __syncthreads();
    int cur = 0;
    for (int t=0; t<nt; t++){
        if (t+1 < nt){
            int k0 = (t+1)*16;
            if (arow < p.M){
                const float* pa = A + (long)arow*p.lda + k0;
                ra[0]=*(const float4*)pa; ra[1]=*(const float4*)(pa+4);
                ra[2]=*(const float4*)(pa+8); ra[3]=*(const float4*)(pa+12);
            } else { ra[0]=z4; ra[1]=z4; ra[2]=z4; ra[3]=z4; }
            const float* pb = B + (long)(k0+brow)*p.ldb + col0 + bc0*4;
            rb0 = *(const float4*)pb; rb1 = *(const float4*)(pb+4);
        }
        #pragma unroll
        for (int kk=0; kk<16; kk++){
            float4 a0 = *(const float4*)&As[cur][kk][ty*8];
            float4 a1 = *(const float4*)&As[cur][kk][ty*8+4];
            ulonglong2 b0 = *(const ulonglong2*)&Bs[cur][kk][pb0];
            ulonglong2 b1 = *(const ulonglong2*)&Bs[cur][kk][pb1];
            u64 ap;
            ap=pack2(a0.x,a0.x); acc[0][0]=ffma2(ap,b0.x,acc[0][0]); acc[0][1]=ffma2(ap,b0.y,acc[0][1]); acc[0][2]=ffma2(ap,b1.x,acc[0][2]); acc[0][3]=ffma2(ap,b1.y,acc[0][3]);
            ap=pack2(a0.y,a0.y); acc[1][0]=ffma2(ap,b0.x,acc[1][0]); acc[1][1]=ffma2(ap,b0.y,acc[1][1]); acc[1][2]=ffma2(ap,b1.x,acc[1][2]); acc[1][3]=ffma2(ap,b1.y,acc[1][3]);
            ap=pack2(a0.z,a0.z); acc[2][0]=ffma2(ap,b0.x,acc[2][0]); acc[2][1]=ffma2(ap,b0.y,acc[2][1]); acc[2][2]=ffma2(ap,b1.x,acc[2][2]); acc[2][3]=ffma2(ap,b1.y,acc[2][3]);
            ap=pack2(a0.w,a0.w); acc[3][0]=ffma2(ap,b0.x,acc[3][0]); acc[3][1]=ffma2(ap,b0.y,acc[3][1]); acc[3][2]=ffma2(ap,b1.x,acc[3][2]); acc[3][3]=ffma2(ap,b1.y,acc[3][3]);
            ap=pack2(a1.x,a1.x); acc[4][0]=ffma2(ap,b0.x,acc[4][0]); acc[4][1]=ffma2(ap,b0.y,acc[4][1]); acc[4][2]=ffma2(ap,b1.x,acc[4][2]); acc[4][3]=ffma2(ap,b1.y,acc[4][3]);
            ap=pack2(a1.y,a1.y); acc[5][0]=ffma2(ap,b0.x,acc[5][0]); acc[5][1]=ffma2(ap,b0.y,acc[5][1]); acc[5][2]=ffma2(ap,b1.x,acc[5][2]); acc[5][3]=ffma2(ap,b1.y,acc[5][3]);
            ap=pack2(a1.z,a1.z); acc[6][0]=ffma2(ap,b0.x,acc[6][0]); acc[6][1]=ffma2(ap,b0.y,acc[6][1]); acc[6][2]=ffma2(ap,b1.x,acc[6][2]); acc[6][3]=ffma2(ap,b1.y,acc[6][3]);
            ap=pack2(a1.w,a1.w); acc[7][0]=ffma2(ap,b0.x,acc[7][0]); acc[7][1]=ffma2(ap,b0.y,acc[7][1]); acc[7][2]=ffma2(ap,b1.x,acc[7][2]); acc[7][3]=ffma2(ap,b1.y,acc[7][3]);
        }
        if (t+1 < nt){
            int nb = cur ^ 1;
            #pragma unroll
            for (int j=0;j<4;j++){
                As[nb][j*4+0][tid]=ra[j].x; As[nb][j*4+1][tid]=ra[j].y;
                As[nb][j*4+2][tid]=ra[j].z; As[nb][j*4+3][tid]=ra[j].w;
            }
            *(float4*)&Bs[nb][brow][pb0] = rb0;
            *(float4*)&Bs[nb][brow][pb1] = rb1;
            __syncthreads();
            cur = nb;
        }
    }
    int colb = col0 + tx*8;
    float4 bia0, bia1;
    if (p.SPLIT == 1 && p.bias){
        bia0 = *(const float4*)(p.bias + colb);
        bia1 = *(const float4*)(p.bias + colb + 4);
    } else { bia0 = z4; bia1 = z4; }
    #pragma unroll
    for (int i=0;i<8;i++){
        int r = row0 + ty*8 + i;
        if (r >= p.M) continue;
        float2 v0 = unpack2(acc[i][0]), v1 = unpack2(acc[i][1]);
        float2 v2 = unpack2(acc[i][2]), v3 = unpack2(acc[i][3]);
        float4 o0 = make_float4(v0.x+bia0.x, v0.y+bia0.y, v1.x+bia0.z, v1.y+bia0.w);
        float4 o1 = make_float4(v2.x+bia1.x, v2.y+bia1.y, v3.x+bia1.z, v3.y+bia1.w);
        if (p.gelu){
            o0.x*=normcdff(o0.x); o0.y*=normcdff(o0.y); o0.z*=normcdff(o0.z); o0.w*=normcdff(o0.w);
            o1.x*=normcdff(o1.x); o1.y*=normcdff(o1.y); o1.z*=normcdff(o1.z); o1.w*=normcdff(o1.w);
        }
        *(float4*)(C + (long)r*p.ldc + colb)     = o0;
        *(float4*)(C + (long)r*p.ldc + colb + 4) = o1;
    }
}

// ---- flash attention: one (b,head,cam) per block, q-tile 128, 256 threads ----
#define QS_OFF 0
#define KS_OFF 4096
#define VT_OFF 8704
#define PS_OFF 13056
#define CS_OFF 21760
#define FL_SMEM (21888*4)

__global__ __launch_bounds__(256,1) void flash_kernel(
    const float* __restrict__ qf, const float* __restrict__ kf,
    const float* __restrict__ vf, float* __restrict__ ao, float* __restrict__ fac)
{
    extern __shared__ float sm[];
    float* Qs    = sm + QS_OFF;   // [128][32] XOR-swizzled chunks
    float* KsB   = sm + KS_OFF;   // [2][64][36]
    float* VtB   = sm + VT_OFF;   // [2][32][68] (V transposed)
    float* Ps    = sm + PS_OFF;   // [128][68], col ^ ((row>>3 &1)<<4)
    float* corrS = sm + CS_OFF;   // [128]

    int yy = blockIdx.y;
    int cam = yy % 6; int bm = yy / 6; int b = bm >> 3, m = bm & 7;
    int q0 = blockIdx.x * 128;
    int tid = threadIdx.x;

    int kg = tid & 15, rg = tid >> 4;     // QK mapping
    int rgx = (rg & 1) << 4;              // Ps store column XOR
    int ks = tid >> 7, low = tid & 127;   // PV mapping
    int orow = low >> 3, oc = low & 7;
    int orx = (orow & 1) << 4;            // Ps read column XOR
    int qr = tid >> 1, qh = tid & 1;      // Q fill
    int fr = tid >> 2, fq = tid & 3;      // K/V fill

    const float scale = 0.17677669529663689f;
    const float4 z4 = make_float4(0.f,0.f,0.f,0.f);

    const float* qb = qf + ((long)(b*NCAM+cam)*HWQ)*DIM + m*DH;
    const float* kb = kf + ((long)(b*NCAM+cam)*PK)*DIM + m*DH;
    const float* vb = vf + ((long)(b*NCAM+cam)*PK)*DIM + m*DH;

    {   // load Q + tile0 K/V
        bool qok = (q0 + qr) < HWQ;
        const float* qp = qb + (long)(q0+qr)*DIM + qh*16;
        float4 q0r = qok ? *(const float4*)(qp)     : z4;
        float4 q1r = qok ? *(const float4*)(qp + 4) : z4;
        float4 q2r = qok ? *(const float4*)(qp + 8) : z4;
        float4 q3r = qok ? *(const float4*)(qp +12) : z4;
        float4 kr0 = *(const float4*)(kb + (long)fr*DIM + fq*8);
        float4 kr1 = *(const float4*)(kb + (long)fr*DIM + fq*8 + 4);
        float4 vr0 = *(const float4*)(vb + (long)fr*DIM + fq*8);
        float4 vr1 = *(const float4*)(vb + (long)fr*DIM + fq*8 + 4);
        int rl = qr & 7;
        q0r.x*=scale; q0r.y*=scale; q0r.z*=scale; q0r.w*=scale;
        q1r.x*=scale; q1r.y*=scale; q1r.z*=scale; q1r.w*=scale;
        q2r.x*=scale; q2r.y*=scale; q2r.z*=scale; q2r.w*=scale;
        q3r.x*=scale; q3r.y*=scale; q3r.z*=scale; q3r.w*=scale;
        *(float4*)(Qs + qr*32 + (((qh*4+0)^rl)<<2)) = q0r;
        *(float4*)(Qs + qr*32 + (((qh*4+1)^rl)<<2)) = q1r;
        *(float4*)(Qs + qr*32 + (((qh*4+2)^rl)<<2)) = q2r;
        *(float4*)(Qs + qr*32 + (((qh*4+3)^rl)<<2)) = q3r;
        *(float4*)(KsB + fr*36 + fq*8)     = kr0;
        *(float4*)(KsB + fr*36 + fq*8 + 4) = kr1;
        VtB[(fq*8+0)*68 + fr] = vr0.x; VtB[(fq*8+1)*68 + fr] = vr0.y;
        VtB[(fq*8+2)*68 + fr] = vr0.z; VtB[(fq*8+3)*68 + fr] = vr0.w;
        VtB[(fq*8+4)*68 + fr] = vr1.x; VtB[(fq*8+5)*68 + fr] = vr1.y;
        VtB[(fq*8+6)*68 + fr] = vr1.z; VtB[(fq*8+7)*68 + fr] = vr1.w;
    }
    __syncthreads();

    float mrow[8], lrow[8];
    #pragma unroll
    for (int i=0;i<8;i++){ mrow[i] = -1e30f; lrow[i] = 0.f; }
    u64 acc[8][4];
    #pragma unroll
    for (int i=0;i<8;i++)
        #pragma unroll
        for (int s=0;s<4;s++) acc[i][s] = 0ULL;

    float4 kr0, kr1, vr0, vr1;
    for (int kt=0; kt<10; kt++){
        int cur = kt & 1;
        if (kt < 9){
            int kn = (kt+1)*64;
            bool ok = (kn + fr) < PK;
            const float* kp = kb + (long)(kn+fr)*DIM + fq*8;
            const float* vp = vb + (long)(kn+fr)*DIM + fq*8;
            kr0 = ok ? *(const float4*)kp     : z4;
            kr1 = ok ? *(const float4*)(kp+4) : z4;
            vr0 = ok ? *(const float4*)vp     : z4;
            vr1 = ok ? *(const float4*)(vp+4) : z4;
        }
        // QK
        u64 sacc[8][4];
        #pragma unroll
        for (int i=0;i<8;i++)
            #pragma unroll
            for (int j=0;j<4;j++) sacc[i][j] = 0ULL;
        const float* Kc = KsB + cur*2304;
        #pragma unroll
        for (int c4=0;c4<8;c4++){
            ulonglong2 kv[4];
            #pragma unroll
            for (int j=0;j<4;j++)
                kv[j] = *(const ulonglong2*)(Kc + (kg+16*j)*36 + c4*4);
            #pragma unroll
            for (int i=0;i<8;i++){
                ulonglong2 qv = *(const ulonglong2*)(Qs + (rg*8+i)*32 + ((c4 ^ i)<<2));
                #pragma unroll
                for (int j=0;j<4;j++){
                    sacc[i][j] = ffma2(qv.x, kv[j].x, sacc[i][j]);
                    sacc[i][j] = ffma2(qv.y, kv[j].y, sacc[i][j]);
                }
            }
        }
        // online softmax (per-cam independent)
        int kk0 = kt*64;
        #pragma unroll
        for (int i=0;i<8;i++){
            float s_[4]; float tmax = -1e30f;
            #pragma unroll
            for (int j=0;j<4;j++){
                float2 t2 = unpack2(sacc[i][j]);
                float v = t2.x + t2.y;
                if (kk0 + kg + 16*j >= PK) v = -1e30f;
                s_[j] = v; tmax = fmaxf(tmax, v);
            }
            #pragma unroll
            for (int off=1; off<16; off<<=1)
                tmax = fmaxf(tmax, __shfl_xor_sync(0xffffffffu, tmax, off));
            float mnew = fmaxf(mrow[i], tmax);
            float corr = __expf(mrow[i] - mnew);
            float rsum = 0.f;
            #pragma unroll
            for (int j=0;j<4;j++){
                float pv = __expf(s_[j] - mnew);
                rsum += pv;
                Ps[(rg*8+i)*68 + ((kg + 16*j) ^ rgx)] = pv;
            }
            #pragma unroll
            for (int off=1; off<16; off<<=1)
                rsum += __shfl_xor_sync(0xffffffffu, rsum, off);
            lrow[i] = lrow[i]*corr + rsum;
            mrow[i] = mnew;
            if (kg == 0) corrS[rg*8+i] = corr;
        }
        __syncthreads();
        // PV (k-split 2)
        #pragma unroll
        for (int i=0;i<8;i++){
            float c = corrS[orow*8+i];
            u64 cp = pack2(c, c);
            #pragma unroll
            for (int s=0;s<4;s++) acc[i][s] = fmul2(acc[i][s], cp);
        }
        const float* Vc = VtB + cur*2176;
        #pragma unroll
        for (int t=0;t<8;t++){
            int k4 = (ks*8 + t)*4;
            ulonglong2 vv[4];
            #pragma unroll
            for (int s=0;s<4;s++)
                vv[s] = *(const ulonglong2*)(Vc + (oc+8*s)*68 + k4);
            #pragma unroll
            for (int i=0;i<8;i++){
                ulonglong2 pp = *(const ulonglong2*)(Ps + (orow*8+i)*68 + (k4 ^ orx));
                #pragma unroll
                for (int s=0;s<4;s++){
                    acc[i][s] = ffma2(pp.x, vv[s].x, acc[i][s]);
                    acc[i][s] = ffma2(pp.y, vv[s].y, acc[i][s]);
                }
            }
        }
        // stage prefetched tile
        if (kt < 9){
            int nb = cur ^ 1;
            *(float4*)(KsB + nb*2304 + fr*36 + fq*8)     = kr0;
            *(float4*)(KsB + nb*2304 + fr*36 + fq*8 + 4) = kr1;
            float* Vn = VtB + nb*2176;
            Vn[(fq*8+0)*68 + fr] = vr0.x; Vn[(fq*8+1)*68 + fr] = vr0.y;
            Vn[(fq*8+2)*68 + fr] = vr0.z; Vn[(fq*8+3)*68 + fr] = vr0.w;
            Vn[(fq*8+4)*68 + fr] = vr1.x; Vn[(fq*8+5)*68 + fr] = vr1.y;
            Vn[(fq*8+6)*68 + fr] = vr1.z; Vn[(fq*8+7)*68 + fr] = vr1.w;
        }
        __syncthreads();
    }

    // fold halves and store unnormalized output + factors
    float o[8][4];
    #pragma unroll
    for (int i=0;i<8;i++)
        #pragma unroll
        for (int s=0;s<4;s++){
            float2 t = unpack2(acc[i][s]);
            o[i][s] = t.x + t.y;
        }
    if (ks == 1){
        #pragma unroll
        for (int i=0;i<8;i++)
            #pragma unroll
            for (int s=0;s<4;s++)
                Ps[(orow*8+i)*33 + oc + 8*s] = o[i][s];
    }
    __syncthreads();
    if (ks == 0){
        #pragma unroll
        for (int i=0;i<8;i++){
            int qq = q0 + orow*8 + i;
            if (qq >= HWQ) continue;
            long base = ((long)b*HWQ + qq)*ND + cam*DIM + m*DH;
            #pragma unroll
            for (int s=0;s<4;s++)
                ao[base + oc + 8*s] = o[i][s] + Ps[(orow*8+i)*33 + oc + 8*s];
        }
    }
    if (kg == 0){
        #pragma unroll
        for (int i=0;i<8;i++){
            int qq = q0 + rg*8 + i;
            if (qq >= HWQ) continue;
            long f0 = ((long)b*HWQ + qq)*96;
            fac[f0 + cam*8 + m]      = mrow[i];
            fac[f0 + 48 + cam*8 + m] = lrow[i];
        }
    }
}

__global__ void ln1536_kernel(const float* __restrict__ x, const float* __restrict__ fac,
                              const float* __restrict__ g, const float* __restrict__ b,
                              float* __restrict__ y){
    __shared__ float sh[8];
    __shared__ float bmu, brs;
    __shared__ float f48[48];
    long row = blockIdx.x;
    const float* p = x + row * (long)ND;
    const float* fr = fac + row * 96;
    int tid = threadIdx.x;
    if (tid < 48){
        int mm = tid & 7;
        float mx = fr[mm];
        #pragma unroll
        for (int c=1;c<6;c++) mx = fmaxf(mx, fr[c*8+mm]);
        float den = 0.f;
        #pragma unroll
        for (int c=0;c<6;c++) den += fr[48+c*8+mm] * __expf(fr[c*8+mm]-mx);
        f48[tid] = __expf(fr[tid]-mx) / den;
    }
    __syncthreads();
    float vals[6]; float s = 0.f;
    #pragma unroll
    for (int i=0;i<6;i++){
        int c = tid + i*256;
        float fv = f48[((c>>8)<<3) + ((c>>5)&7)];
        vals[i] = p[c] * fv; s += vals[i];
    }
    s = warpRedSum(s);
    if ((tid & 31) == 0) sh[tid>>5] = s;
    __syncthreads();
    if (tid == 0){ float t=0.f; for (int i=0;i<8;i++) t += sh[i]; bmu = t / (float)ND; }
    __syncthreads();
    float mu = bmu, vs = 0.f;
    #pragma unroll
    for (int i=0;i<6;i++){ float d = vals[i]-mu; vs += d*d; }
    vs = warpRedSum(vs);
    if ((tid & 31) == 0) sh[tid>>5] = vs;
    __syncthreads();
    if (tid == 0){ float t=0.f; for (int i=0;i<8;i++) t += sh[i]; brs = rsqrtf(t/(float)ND + 1e-5f); }
    __syncthreads();
    float rs = brs;
    float* q = y + row * (long)ND;
    #pragma unroll
    for (int i=0;i<6;i++){ int c = tid + i*256; q[c] = (vals[i]-mu)*rs*g[c] + b[c]; }
}

__global__ void reduce_proj_kernel(const float* __restrict__ p1, const float* __restrict__ p2,
                                   const float* __restrict__ baddq, const float* __restrict__ bproj,
                                   float* __restrict__ xb){
    long idx = (long)blockIdx.x * 256 + threadIdx.x;
    const long MN = (long)NB*HWQ*DIM;
    if (idx >= MN) return;
    int c = (int)(idx & 255);
    float v = bproj[c] + baddq[c];
    v += p1[idx] + p1[idx+MN] + p1[idx+2*MN];
    v += p2[idx] + p2[idx+MN] + p2[idx+2*MN];
    xb[idx] = v;
}

__global__ void final_kernel(const float* __restrict__ p3, const float* __restrict__ b2,
                             const float* __restrict__ x,
                             const float* __restrict__ g, const float* __restrict__ bb,
                             float* __restrict__ out){
    __shared__ float sh[8];
    __shared__ float bmu, brs;
    long row = blockIdx.x;
    const long MN = (long)NB*HWQ*DIM;
    int c = threadIdx.x;
    float v = p3[row*(long)DIM + c] + p3[MN + row*(long)DIM + c] + b2[c];
    float s = warpRedSum(v);
    if ((c & 31) == 0) sh[c>>5] = s;
    __syncthreads();
    if (c == 0){ float m=0.f; for (int i=0;i<8;i++) m += sh[i]; bmu = m / (float)DIM; }
    __syncthreads();
    float mu = bmu;
    float d = v - mu;
    float vs = warpRedSum(d*d);
    if ((c & 31) == 0) sh[c>>5] = vs;
    __syncthreads();
    if (c == 0){ float m=0.f; for (int i=0;i<8;i++) m += sh[i]; brs = rsqrtf(m/(float)DIM + 1e-5f); }
    __syncthreads();
    float y = d * brs * g[c] + bb[c] + x[row*(long)DIM + c];
    int b = (int)(row / HWQ), p = (int)(row % HWQ);
    out[((long)(b*DIM + c))*HWQ + p] = y;
}

static float* sym(const void* symbol){
    void* p = nullptr;
    cudaGetSymbolAddress(&p, symbol);
    return (float*)p;
}

static GemmP zeroP(){ GemmP p; memset(&p, 0, sizeof(p)); p.D1 = 1; p.SPLIT = 1; return p; }

static void launch_gemm(const GemmP& p, int batches){
    dim3 grid(p.N/64, (p.M+127)/128, batches * p.SPLIT);
    gemm_tc<<<grid, 128>>>(p);
}

extern "C" void kernel_launch(void* const* d_in, const int* in_sizes, int n_in,
                              void* d_out, int out_size){
    const float* q     = (const float*)d_in[0];
    const float* k     = (const float*)d_in[1];
    const float* v     = (const float*)d_in[2];
    const float* Wq    = (const float*)d_in[3];
    const float* bq    = (const float*)d_in[4];
    const float* Wk    = (const float*)d_in[5];
    const float* bk    = (const float*)d_in[6];
    const float* Wv    = (const float*)d_in[7];
    const float* bv    = (const float*)d_in[8];
    const float* Wproj = (const float*)d_in[9];
    const float* bproj = (const float*)d_in[10];
    const float* Waddq = (const float*)d_in[11];
    const float* baddq = (const float*)d_in[12];
    const float* W1    = (const float*)d_in[13];
    const float* b1    = (const float*)d_in[14];
    const float* W2    = (const float*)d_in[15];
    const float* b2    = (const float*)d_in[16];
    const float* g_pre = (const float*)d_in[17];
    const float* b_pre = (const float*)d_in[18];
    const float* g_nrm = (const float*)d_in[19];
    const float* b_nrm = (const float*)d_in[20];
    float* out = (float*)d_out;

    float* qT    = sym(g_qT);
    float* kpool = sym(g_kpool);
    float* vpool = sym(g_vpool);
    float* qf    = sym(g_qf);
    float* kf    = sym(g_kf);
    float* vf    = sym(g_vf);
    float* ao    = sym(g_attno);
    float* fac   = sym(g_fac);
    float* lnb   = sym(g_lnbuf);
    float* xb    = sym(g_xbuf);
    float* h1    = sym(g_h1);
    float* part1 = sym(g_part1);
    float* part2 = sym(g_part2);
    float* part3 = sym(g_part3);

    cudaFuncSetAttribute(flash_kernel, cudaFuncAttributeMaxDynamicSharedMemorySize, FL_SMEM);

    {
        dim3 grid((HWQ+31)/32, DIM/32, NB*NCAM);
        transpose_q_kernel<<<grid, dim3(32,8)>>>(q, qT);
    }
    {
        long total = (long)NB*NCAM*DIM*PK;
        int blocks = (int)((total + 255) / 256);
        pool_kernel<<<blocks, 256>>>(k, kpool);
        pool_kernel<<<blocks, 256>>>(v, vpool);
    }
    {   // add_q partials, split-K x3
        GemmP p = zeroP();
        p.A = qT; p.lda = ND; p.B = Waddq; p.ldb = DIM;
        p.C = part1; p.ldc = DIM; p.M = NB*HWQ; p.N = DIM;
        p.K = ND/3; p.SPLIT = 3; p.csplit = (long)NB*HWQ*DIM;
        launch_gemm(p, 1);
    }
    {   // qf per (b,cam)
        GemmP p = zeroP();
        p.A = qT; p.lda = ND; p.a0 = (long)HWQ*ND; p.a1 = DIM;
        p.B = Wq; p.ldb = DIM; p.bias = bq;
        p.C = qf; p.ldc = DIM; p.c0 = (long)NCAM*HWQ*DIM; p.c1 = (long)HWQ*DIM;
        p.M = HWQ; p.N = DIM; p.K = DIM; p.D1 = NCAM;
        launch_gemm(p, NB*NCAM);
    }
    {   // kf, vf per (b,cam)
        GemmP p = zeroP();
        p.A = kpool; p.lda = ND; p.a0 = (long)PK*ND; p.a1 = DIM;
        p.B = Wk; p.ldb = DIM; p.bias = bk;
        p.C = kf; p.ldc = DIM; p.c0 = (long)NCAM*PK*DIM; p.c1 = (long)PK*DIM;
        p.M = PK; p.N = DIM; p.K = DIM; p.D1 = NCAM;
        launch_gemm(p, NB*NCAM);
        p.A = vpool; p.B = Wv; p.bias = bv; p.C = vf;
        launch_gemm(p, NB*NCAM);
    }
    {   // flash attention, per-cam blocks
        dim3 grid((HWQ+127)/128, NB*NHEAD*NCAM);
        flash_kernel<<<grid, 256, FL_SMEM>>>(qf, kf, vf, ao, fac);
    }
    ln1536_kernel<<<NB*HWQ, 256>>>(ao, fac, g_pre, b_pre, lnb);
    {   // proj partials, split-K x3
        GemmP p = zeroP();
        p.A = lnb; p.lda = ND; p.B = Wproj; p.ldb = DIM;
        p.C = part2; p.ldc = DIM; p.M = NB*HWQ; p.N = DIM;
        p.K = ND/3; p.SPLIT = 3; p.csplit = (long)NB*HWQ*DIM;
        launch_gemm(p, 1);
    }
    {
        long MN = (long)NB*HWQ*DIM;
        reduce_proj_kernel<<<(int)((MN+255)/256), 256>>>(part1, part2, baddq, bproj, xb);
    }
    {   // ffn1 + gelu
        GemmP p = zeroP();
        p.A = xb; p.lda = DIM; p.B = W1; p.ldb = 2*DIM; p.bias = b1; p.gelu = 1;
        p.C = h1; p.ldc = 2*DIM; p.M = NB*HWQ; p.N = 2*DIM; p.K = DIM;
        launch_gemm(p, 1);
    }
    {   // ffn2 partials, split-K x2
        GemmP p = zeroP();
        p.A = h1; p.lda = 2*DIM; p.B = W2; p.ldb = DIM;
        p.C = part3; p.ldc = DIM; p.M = NB*HWQ; p.N = DIM;
        p.K = DIM; p.SPLIT = 2; p.csplit = (long)NB*HWQ*DIM;
        launch_gemm(p, 1);
    }
    final_kernel<<<NB*HWQ, 256>>>(part3, b2, xb, g_nrm, b_nrm, out);
}

// round 10
// speedup vs baseline: 1.6252x; 1.0369x over previous
#include <cuda_runtime.h>
#include <math.h>
#include <string.h>

#define NB    2
#define NCAM  6
#define DIM   256
#define HWQ   2500
#define PK    625
#define PKP   628   // padded k-stride for pooled tensors (multiple of 4)
#define NHEAD 8
#define DH    32
#define ND    1536

typedef unsigned long long u64;

__device__ __forceinline__ u64 ffma2(u64 a, u64 b, u64 c){
    u64 d; asm("fma.rn.f32x2 %0, %1, %2, %3;" : "=l"(d) : "l"(a), "l"(b), "l"(c)); return d;
}
__device__ __forceinline__ u64 fmul2(u64 a, u64 b){
    u64 d; asm("mul.rn.f32x2 %0, %1, %2;" : "=l"(d) : "l"(a), "l"(b)); return d;
}
__device__ __forceinline__ u64 pack2(float x, float y){
    u64 d; asm("mov.b64 %0, {%1, %2};" : "=l"(d) : "f"(x), "f"(y)); return d;
}
__device__ __forceinline__ float2 unpack2(u64 v){
    float2 r; asm("mov.b64 {%0, %1}, %2;" : "=f"(r.x), "=f"(r.y) : "l"(v)); return r;
}

__device__ float g_kpool [(long)NB*NCAM*DIM*PKP];
__device__ float g_vpool [(long)NB*NCAM*DIM*PKP];
__device__ float g_qf    [(long)NB*NCAM*HWQ*DIM];
__device__ float g_kf    [(long)NB*NCAM*PK*DIM];
__device__ float g_vf    [(long)NB*NCAM*PK*DIM];
__device__ float g_attno [(long)NB*HWQ*ND];
__device__ float g_fac   [(long)NB*HWQ*96];
__device__ float g_lnbuf [(long)NB*HWQ*ND];
__device__ float g_xbuf  [(long)NB*HWQ*DIM];
__device__ float g_h1    [(long)NB*HWQ*2*DIM];
__device__ float g_part1 [(long)3*NB*HWQ*DIM];
__device__ float g_part2 [(long)3*NB*HWQ*DIM];
__device__ float g_part3 [(long)2*NB*HWQ*DIM];

__device__ __forceinline__ float warpRedSum(float v){
    #pragma unroll
    for (int o=16;o;o>>=1) v += __shfl_xor_sync(0xffffffffu, v, o);
    return v;
}

// ---- 2x2 pool, natural (b,cam,c,kk) output with padded k-stride ----
__global__ void pool_kernel(const float* __restrict__ src, float* __restrict__ dst){
    long idx = (long)blockIdx.x * blockDim.x + threadIdx.x;
    const long total = (long)NB*NCAM*DIM*PK;
    if (idx >= total) return;
    int kk  = (int)(idx % PK);  long t = idx / PK;
    int c   = (int)(t % DIM);   t /= DIM;
    int cam = (int)(t % NCAM);
    int b   = (int)(t / NCAM);
    int i = kk / 25, j = kk % 25;
    const float* p = src + ((long)((b*NCAM+cam)*DIM + c))*HWQ + (2*i)*50 + 2*j;
    float v = 0.25f * (p[0] + p[1] + p[50] + p[51]);
    dst[((long)((b*NCAM+cam)*DIM + c))*PKP + kk] = v;
}

struct GemmP {
    const float* A; const float* B; const float* bias; float* C;
    int lda, ldb, ldc;
    int M, N, K;
    int gelu, D1, SPLIT, ATR;   // ATR: A stored [k][r], lda = k-stride
    long a0, a1, c0, c1, csplit;
};

__global__ __launch_bounds__(128,4) void gemm_tc(GemmP p){
    __shared__ float As[2][16][128];
    __shared__ float Bs[2][16][64];

    int z = blockIdx.z;
    int s = z % p.SPLIT; int zz = z / p.SPLIT;
    int i1 = zz % p.D1;  int i0 = zz / p.D1;
    long askip = (long)s*p.K*(p.ATR ? (long)p.lda : 1L);
    const float* A = p.A + i0*p.a0 + i1*p.a1 + askip;
    const float* B = p.B + (long)s*p.K*p.ldb;
    float*       C = p.C + i0*p.c0 + i1*p.c1 + (long)s*p.csplit;

    int tid = threadIdx.x;
    int tx = tid & 7, ty = tid >> 3;
    int row0 = blockIdx.y*128, col0 = blockIdx.x*64;

    int arow = row0 + tid;
    bool aok = arow < p.M;
    int brow = tid >> 3;
    int bc0  = (tid & 7) * 2;
    int pb0  = (bc0 ^ (bc0 >> 3)) * 4;
    int pb1  = ((bc0+1) ^ ((bc0+1) >> 3)) * 4;

    u64 acc[8][4];
    #pragma unroll
    for (int i=0;i<8;i++)
        #pragma unroll
        for (int j=0;j<4;j++) acc[i][j] = 0ULL;

    const float4 z4 = make_float4(0.f,0.f,0.f,0.f);
    float av[16]; float4 rb0, rb1;
    const float* atc = p.ATR ? (A + arow) : (A + (aok ? (long)arow*p.lda : 0));

    int nt = p.K / 16;
    // prefetch tile 0
    if (!p.ATR){
        if (aok){
            float4 r0=*(const float4*)atc, r1=*(const float4*)(atc+4);
            float4 r2=*(const float4*)(atc+8), r3=*(const float4*)(atc+12);
            av[0]=r0.x;av[1]=r0.y;av[2]=r0.z;av[3]=r0.w;
            av[4]=r1.x;av[5]=r1.y;av[6]=r1.z;av[7]=r1.w;
            av[8]=r2.x;av[9]=r2.y;av[10]=r2.z;av[11]=r2.w;
            av[12]=r3.x;av[13]=r3.y;av[14]=r3.z;av[15]=r3.w;
        } else {
            #pragma unroll
            for (int j=0;j<16;j++) av[j]=0.f;
        }
    } else {
        #pragma unroll
        for (int j=0;j<16;j++) av[j] = aok ? atc[(long)j*p.lda] : 0.f;
    }
    {
        const float* pb = B + (long)brow*p.ldb + col0 + bc0*4;
        rb0 = *(const float4*)pb; rb1 = *(const float4*)(pb+4);
    }
    {
        #pragma unroll
        for (int j=0;j<16;j++) As[0][j][tid]=av[j];
        *(float4*)&Bs[0][brow][pb0] = rb0;
        *(float4*)&Bs[0][brow][pb1] = rb1;
    }
    __syncthreads();
    int cur = 0;
    for (int t=0; t<nt; t++){
        if (t+1 < nt){
            int k0 = (t+1)*16;
            if (!p.ATR){
                if (aok){
                    const float* pa = atc + k0;
                    float4 r0=*(const float4*)pa, r1=*(const float4*)(pa+4);
                    float4 r2=*(const float4*)(pa+8), r3=*(const float4*)(pa+12);
                    av[0]=r0.x;av[1]=r0.y;av[2]=r0.z;av[3]=r0.w;
                    av[4]=r1.x;av[5]=r1.y;av[6]=r1.z;av[7]=r1.w;
                    av[8]=r2.x;av[9]=r2.y;av[10]=r2.z;av[11]=r2.w;
                    av[12]=r3.x;av[13]=r3.y;av[14]=r3.z;av[15]=r3.w;
                }
            } else {
                #pragma unroll
                for (int j=0;j<16;j++) av[j] = aok ? atc[(long)(k0+j)*p.lda] : 0.f;
            }
            const float* pb = B + (long)(k0+brow)*p.ldb + col0 + bc0*4;
            rb0 = *(const float4*)pb; rb1 = *(const float4*)(pb+4);
        }
        #pragma unroll
        for (int kk=0; kk<16; kk++){
            float4 a0 = *(const float4*)&As[cur][kk][ty*8];
            float4 a1 = *(const float4*)&As[cur][kk][ty*8+4];
            ulonglong2 b0 = *(const ulonglong2*)&Bs[cur][kk][pb0];
            ulonglong2 b1 = *(const ulonglong2*)&Bs[cur][kk][pb1];
            u64 ap;
            ap=pack2(a0.x,a0.x); acc[0][0]=ffma2(ap,b0.x,acc[0][0]); acc[0][1]=ffma2(ap,b0.y,acc[0][1]); acc[0][2]=ffma2(ap,b1.x,acc[0][2]); acc[0][3]=ffma2(ap,b1.y,acc[0][3]);
            ap=pack2(a0.y,a0.y); acc[1][0]=ffma2(ap,b0.x,acc[1][0]); acc[1][1]=ffma2(ap,b0.y,acc[1][1]); acc[1][2]=ffma2(ap,b1.x,acc[1][2]); acc[1][3]=ffma2(ap,b1.y,acc[1][3]);
            ap=pack2(a0.z,a0.z); acc[2][0]=ffma2(ap,b0.x,acc[2][0]); acc[2][1]=ffma2(ap,b0.y,acc[2][1]); acc[2][2]=ffma2(ap,b1.x,acc[2][2]); acc[2][3]=ffma2(ap,b1.y,acc[2][3]);
            ap=pack2(a0.w,a0.w); acc[3][0]=ffma2(ap,b0.x,acc[3][0]); acc[3][1]=ffma2(ap,b0.y,acc[3][1]); acc[3][2]=ffma2(ap,b1.x,acc[3][2]); acc[3][3]=ffma2(ap,b1.y,acc[3][3]);
            ap=pack2(a1.x,a1.x); acc[4][0]=ffma2(ap,b0.x,acc[4][0]); acc[4][1]=ffma2(ap,b0.y,acc[4][1]); acc[4][2]=ffma2(ap,b1.x,acc[4][2]); acc[4][3]=ffma2(ap,b1.y,acc[4][3]);
            ap=pack2(a1.y,a1.y); acc[5][0]=ffma2(ap,b0.x,acc[5][0]); acc[5][1]=ffma2(ap,b0.y,acc[5][1]); acc[5][2]=ffma2(ap,b1.x,acc[5][2]); acc[5][3]=ffma2(ap,b1.y,acc[5][3]);
            ap=pack2(a1.z,a1.z); acc[6][0]=ffma2(ap,b0.x,acc[6][0]); acc[6][1]=ffma2(ap,b0.y,acc[6][1]); acc[6][2]=ffma2(ap,b1.x,acc[6][2]); acc[6][3]=ffma2(ap,b1.y,acc[6][3]);
            ap=pack2(a1.w,a1.w); acc[7][0]=ffma2(ap,b0.x,acc[7][0]); acc[7][1]=ffma2(ap,b0.y,acc[7][1]); acc[7][2]=ffma2(ap,b1.x,acc[7][2]); acc[7][3]=ffma2(ap,b1.y,acc[7][3]);
        }
        if (t+1 < nt){
            int nb = cur ^ 1;
            #pragma unroll
            for (int j=0;j<16;j++) As[nb][j][tid]=av[j];
            *(float4*)&Bs[nb][brow][pb0] = rb0;
            *(float4*)&Bs[nb][brow][pb1] = rb1;
            __syncthreads();
            cur = nb;
        }
    }
    int colb = col0 + tx*8;
    float4 bia0, bia1;
    if (p.SPLIT == 1 && p.bias){
        bia0 = *(const float4*)(p.bias + colb);
        bia1 = *(const float4*)(p.bias + colb + 4);
    } else { bia0 = z4; bia1 = z4; }
    #pragma unroll
    for (int i=0;i<8;i++){
        int r = row0 + ty*8 + i;
        if (r >= p.M) continue;
        float2 v0 = unpack2(acc[i][0]), v1 = unpack2(acc[i][1]);
        float2 v2 = unpack2(acc[i][2]), v3 = unpack2(acc[i][3]);
        float4 o0 = make_float4(v0.x+bia0.x, v0.y+bia0.y, v1.x+bia0.z, v1.y+bia0.w);
        float4 o1 = make_float4(v2.x+bia1.x, v2.y+bia1.y, v3.x+bia1.z, v3.y+bia1.w);
        if (p.gelu){
            o0.x*=normcdff(o0.x); o0.y*=normcdff(o0.y); o0.z*=normcdff(o0.z); o0.w*=normcdff(o0.w);
            o1.x*=normcdff(o1.x); o1.y*=normcdff(o1.y); o1.z*=normcdff(o1.z); o1.w*=normcdff(o1.w);
        }
        *(float4*)(C + (long)r*p.ldc + colb)     = o0;
        *(float4*)(C + (long)r*p.ldc + colb + 4) = o1;
    }
}

// ---- flash attention: one (b,head,cam) per block, q-tile 128, 256 threads ----
#define QS_OFF 0
#define KS_OFF 4096
#define VT_OFF 8704
#define PS_OFF 13056
#define CS_OFF 21760
#define FL_SMEM (21888*4)

__global__ __launch_bounds__(256,1) void flash_kernel(
    const float* __restrict__ qf, const float* __restrict__ kf,
    const float* __restrict__ vf, float* __restrict__ ao, float* __restrict__ fac)
{
    extern __shared__ float sm[];
    float* Qs    = sm + QS_OFF;
    float* KsB   = sm + KS_OFF;
    float* VtB   = sm + VT_OFF;
    float* Ps    = sm + PS_OFF;
    float* corrS = sm + CS_OFF;

    int yy = blockIdx.y;
    int cam = yy % 6; int bm = yy / 6; int b = bm >> 3, m = bm & 7;
    int q0 = blockIdx.x * 128;
    int tid = threadIdx.x;

    int kg = tid & 15, rg = tid >> 4;
    int rgx = (rg & 1) << 4;
    int ks = tid >> 7, low = tid & 127;
    int orow = low >> 3, oc = low & 7;
    int orx = (orow & 1) << 4;
    int qr = tid >> 1, qh = tid & 1;
    int fr = tid >> 2, fq = tid & 3;

    const float scale = 0.17677669529663689f;
    const float4 z4 = make_float4(0.f,0.f,0.f,0.f);

    const float* qb = qf + ((long)(b*NCAM+cam)*HWQ)*DIM + m*DH;
    const float* kb = kf + ((long)(b*NCAM+cam)*PK)*DIM + m*DH;
    const float* vb = vf + ((long)(b*NCAM+cam)*PK)*DIM + m*DH;

    {
        bool qok = (q0 + qr) < HWQ;
        const float* qp = qb + (long)(q0+qr)*DIM + qh*16;
        float4 q0r = qok ? *(const float4*)(qp)     : z4;
        float4 q1r = qok ? *(const float4*)(qp + 4) : z4;
        float4 q2r = qok ? *(const float4*)(qp + 8) : z4;
        float4 q3r = qok ? *(const float4*)(qp +12) : z4;
        float4 kr0 = *(const float4*)(kb + (long)fr*DIM + fq*8);
        float4 kr1 = *(const float4*)(kb + (long)fr*DIM + fq*8 + 4);
        float4 vr0 = *(const float4*)(vb + (long)fr*DIM + fq*8);
        float4 vr1 = *(const float4*)(vb + (long)fr*DIM + fq*8 + 4);
        int rl = qr & 7;
        q0r.x*=scale; q0r.y*=scale; q0r.z*=scale; q0r.w*=scale;
        q1r.x*=scale; q1r.y*=scale; q1r.z*=scale; q1r.w*=scale;
        q2r.x*=scale; q2r.y*=scale; q2r.z*=scale; q2r.w*=scale;
        q3r.x*=scale; q3r.y*=scale; q3r.z*=scale; q3r.w*=scale;
        *(float4*)(Qs + qr*32 + (((qh*4+0)^rl)<<2)) = q0r;
        *(float4*)(Qs + qr*32 + (((qh*4+1)^rl)<<2)) = q1r;
        *(float4*)(Qs + qr*32 + (((qh*4+2)^rl)<<2)) = q2r;
        *(float4*)(Qs + qr*32 + (((qh*4+3)^rl)<<2)) = q3r;
        *(float4*)(KsB + fr*36 + fq*8)     = kr0;
        *(float4*)(KsB + fr*36 + fq*8 + 4) = kr1;
        VtB[(fq*8+0)*68 + fr] = vr0.x; VtB[(fq*8+1)*68 + fr] = vr0.y;
        VtB[(fq*8+2)*68 + fr] = vr0.z; VtB[(fq*8+3)*68 + fr] = vr0.w;
        VtB[(fq*8+4)*68 + fr] = vr1.x; VtB[(fq*8+5)*68 + fr] = vr1.y;
        VtB[(fq*8+6)*68 + fr] = vr1.z; VtB[(fq*8+7)*68 + fr] = vr1.w;
    }
    __syncthreads();

    float mrow[8], lrow[8];
    #pragma unroll
    for (int i=0;i<8;i++){ mrow[i] = -1e30f; lrow[i] = 0.f; }
    u64 acc[8][4];
    #pragma unroll
    for (int i=0;i<8;i++)
        #pragma unroll
        for (int s=0;s<4;s++) acc[i][s] = 0ULL;

    float4 kr0, kr1, vr0, vr1;
    for (int kt=0; kt<10; kt++){
        int cur = kt & 1;
        if (kt < 9){
            int kn = (kt+1)*64;
            bool ok = (kn + fr) < PK;
            const float* kp = kb + (long)(kn+fr)*DIM + fq*8;
            const float* vp = vb + (long)(kn+fr)*DIM + fq*8;
            kr0 = ok ? *(const float4*)kp     : z4;
            kr1 = ok ? *(const float4*)(kp+4) : z4;
            vr0 = ok ? *(const float4*)vp     : z4;
            vr1 = ok ? *(const float4*)(vp+4) : z4;
        }
        u64 sacc[8][4];
        #pragma unroll
        for (int i=0;i<8;i++)
            #pragma unroll
            for (int j=0;j<4;j++) sacc[i][j] = 0ULL;
        const float* Kc = KsB + cur*2304;
        #pragma unroll
        for (int c4=0;c4<8;c4++){
            ulonglong2 kv[4];
            #pragma unroll
            for (int j=0;j<4;j++)
                kv[j] = *(const ulonglong2*)(Kc + (kg+16*j)*36 + c4*4);
            #pragma unroll
            for (int i=0;i<8;i++){
                ulonglong2 qv = *(const ulonglong2*)(Qs + (rg*8+i)*32 + ((c4 ^ i)<<2));
                #pragma unroll
                for (int j=0;j<4;j++){
                    sacc[i][j] = ffma2(qv.x, kv[j].x, sacc[i][j]);
                    sacc[i][j] = ffma2(qv.y, kv[j].y, sacc[i][j]);
                }
            }
        }
        int kk0 = kt*64;
        #pragma unroll
        for (int i=0;i<8;i++){
            float s_[4]; float tmax = -1e30f;
            #pragma unroll
            for (int j=0;j<4;j++){
                float2 t2 = unpack2(sacc[i][j]);
                float v = t2.x + t2.y;
                if (kk0 + kg + 16*j >= PK) v = -1e30f;
                s_[j] = v; tmax = fmaxf(tmax, v);
            }
            #pragma unroll
            for (int off=1; off<16; off<<=1)
                tmax = fmaxf(tmax, __shfl_xor_sync(0xffffffffu, tmax, off));
            float mnew = fmaxf(mrow[i], tmax);
            float corr = __expf(mrow[i] - mnew);
            float rsum = 0.f;
            #pragma unroll
            for (int j=0;j<4;j++){
                float pv = __expf(s_[j] - mnew);
                rsum += pv;
                Ps[(rg*8+i)*68 + ((kg + 16*j) ^ rgx)] = pv;
            }
            #pragma unroll
            for (int off=1; off<16; off<<=1)
                rsum += __shfl_xor_sync(0xffffffffu, rsum, off);
            lrow[i] = lrow[i]*corr + rsum;
            mrow[i] = mnew;
            if (kg == 0) corrS[rg*8+i] = corr;
        }
        __syncthreads();
        #pragma unroll
        for (int i=0;i<8;i++){
            float c = corrS[orow*8+i];
            u64 cp = pack2(c, c);
            #pragma unroll
            for (int s=0;s<4;s++) acc[i][s] = fmul2(acc[i][s], cp);
        }
        const float* Vc = VtB + cur*2176;
        #pragma unroll
        for (int t=0;t<8;t++){
            int k4 = (ks*8 + t)*4;
            ulonglong2 vv[4];
            #pragma unroll
            for (int s=0;s<4;s++)
                vv[s] = *(const ulonglong2*)(Vc + (oc+8*s)*68 + k4);
            #pragma unroll
            for (int i=0;i<8;i++){
                ulonglong2 pp = *(const ulonglong2*)(Ps + (orow*8+i)*68 + (k4 ^ orx));
                #pragma unroll
                for (int s=0;s<4;s++){
                    acc[i][s] = ffma2(pp.x, vv[s].x, acc[i][s]);
                    acc[i][s] = ffma2(pp.y, vv[s].y, acc[i][s]);
                }
            }
        }
        if (kt < 9){
            int nb = cur ^ 1;
            *(float4*)(KsB + nb*2304 + fr*36 + fq*8)     = kr0;
            *(float4*)(KsB + nb*2304 + fr*36 + fq*8 + 4) = kr1;
            float* Vn = VtB + nb*2176;
            Vn[(fq*8+0)*68 + fr] = vr0.x; Vn[(fq*8+1)*68 + fr] = vr0.y;
            Vn[(fq*8+2)*68 + fr] = vr0.z; Vn[(fq*8+3)*68 + fr] = vr0.w;
            Vn[(fq*8+4)*68 + fr] = vr1.x; Vn[(fq*8+5)*68 + fr] = vr1.y;
            Vn[(fq*8+6)*68 + fr] = vr1.z; Vn[(fq*8+7)*68 + fr] = vr1.w;
        }
        __syncthreads();
    }

    float o[8][4];
    #pragma unroll
    for (int i=0;i<8;i++)
        #pragma unroll
        for (int s=0;s<4;s++){
            float2 t = unpack2(acc[i][s]);
            o[i][s] = t.x + t.y;
        }
    if (ks == 1){
        #pragma unroll
        for (int i=0;i<8;i++)
            #pragma unroll
            for (int s=0;s<4;s++)
                Ps[(orow*8+i)*33 + oc + 8*s] = o[i][s];
    }
    __syncthreads();
    if (ks == 0){
        #pragma unroll
        for (int i=0;i<8;i++){
            int qq = q0 + orow*8 + i;
            if (qq >= HWQ) continue;
            long base = ((long)b*HWQ + qq)*ND + cam*DIM + m*DH;
            #pragma unroll
            for (int s=0;s<4;s++)
                ao[base + oc + 8*s] = o[i][s] + Ps[(orow*8+i)*33 + oc + 8*s];
        }
    }
    if (kg == 0){
        #pragma unroll
        for (int i=0;i<8;i++){
            int qq = q0 + rg*8 + i;
            if (qq >= HWQ) continue;
            long f0 = ((long)b*HWQ + qq)*96;
            fac[f0 + cam*8 + m]      = mrow[i];
            fac[f0 + 48 + cam*8 + m] = lrow[i];
        }
    }
}

__global__ void ln1536_kernel(const float* __restrict__ x, const float* __restrict__ fac,
                              const float* __restrict__ g, const float* __restrict__ b,
                              float* __restrict__ y){
    __shared__ float sh[8];
    __shared__ float bmu, brs;
    __shared__ float f48[48];
    long row = blockIdx.x;
    const float* p = x + row * (long)ND;
    const float* fr = fac + row * 96;
    int tid = threadIdx.x;
    if (tid < 48){
        int mm = tid & 7;
        float mx = fr[mm];
        #pragma unroll
        for (int c=1;c<6;c++) mx = fmaxf(mx, fr[c*8+mm]);
        float den = 0.f;
        #pragma unroll
        for (int c=0;c<6;c++) den += fr[48+c*8+mm] * __expf(fr[c*8+mm]-mx);
        f48[tid] = __expf(fr[tid]-mx) / den;
    }
    __syncthreads();
    float vals[6]; float s = 0.f;
    #pragma unroll
    for (int i=0;i<6;i++){
        int c = tid + i*256;
        float fv = f48[((c>>8)<<3) + ((c>>5)&7)];
        vals[i] = p[c] * fv; s += vals[i];
    }
    s = warpRedSum(s);
    if ((tid & 31) == 0) sh[tid>>5] = s;
    __syncthreads();
    if (tid == 0){ float t=0.f; for (int i=0;i<8;i++) t += sh[i]; bmu = t / (float)ND; }
    __syncthreads();
    float mu = bmu, vs = 0.f;
    #pragma unroll
    for (int i=0;i<6;i++){ float d = vals[i]-mu; vs += d*d; }
    vs = warpRedSum(vs);
    if ((tid & 31) == 0) sh[tid>>5] = vs;
    __syncthreads();
    if (tid == 0){ float t=0.f; for (int i=0;i<8;i++) t += sh[i]; brs = rsqrtf(t/(float)ND + 1e-5f); }
    __syncthreads();
    float rs = brs;
    float* q = y + row * (long)ND;
    #pragma unroll
    for (int i=0;i<6;i++){ int c = tid + i*256; q[c] = (vals[i]-mu)*rs*g[c] + b[c]; }
}

__global__ void reduce_proj_kernel(const float* __restrict__ p1, const float* __restrict__ p2,
                                   const float* __restrict__ baddq, const float* __restrict__ bproj,
                                   float* __restrict__ xb){
    long idx = (long)blockIdx.x * 256 + threadIdx.x;
    const long MN = (long)NB*HWQ*DIM;
    if (idx >= MN) return;
    int c = (int)(idx & 255);
    float v = bproj[c] + baddq[c];
    v += p1[idx] + p1[idx+MN] + p1[idx+2*MN];
    v += p2[idx] + p2[idx+MN] + p2[idx+2*MN];
    xb[idx] = v;
}

__global__ void final_kernel(const float* __restrict__ p3, const float* __restrict__ b2,
                             const float* __restrict__ x,
                             const float* __restrict__ g, const float* __restrict__ bb,
                             float* __restrict__ out){
    __shared__ float sh[8];
    __shared__ float bmu, brs;
    long row = blockIdx.x;
    const long MN = (long)NB*HWQ*DIM;
    int c = threadIdx.x;
    float v = p3[row*(long)DIM + c] + p3[MN + row*(long)DIM + c] + b2[c];
    float s = warpRedSum(v);
    if ((c & 31) == 0) sh[c>>5] = s;
    __syncthreads();
    if (c == 0){ float m=0.f; for (int i=0;i<8;i++) m += sh[i]; bmu = m / (float)DIM; }
    __syncthreads();
    float mu = bmu;
    float d = v - mu;
    float vs = warpRedSum(d*d);
    if ((c & 31) == 0) sh[c>>5] = vs;
    __syncthreads();
    if (c == 0){ float m=0.f; for (int i=0;i<8;i++) m += sh[i]; brs = rsqrtf(m/(float)DIM + 1e-5f); }
    __syncthreads();
    float y = d * brs * g[c] + bb[c] + x[row*(long)DIM + c];
    int b = (int)(row / HWQ), p = (int)(row % HWQ);
    out[((long)(b*DIM + c))*HWQ + p] = y;
}

static float* sym(const void* symbol){
    void* p = nullptr;
    cudaGetSymbolAddress(&p, symbol);
    return (float*)p;
}

static GemmP zeroP(){ GemmP p; memset(&p, 0, sizeof(p)); p.D1 = 1; p.SPLIT = 1; return p; }

static void launch_gemm(const GemmP& p, int batches){
    dim3 grid(p.N/64, (p.M+127)/128, batches * p.SPLIT);
    gemm_tc<<<grid, 128>>>(p);
}

extern "C" void kernel_launch(void* const* d_in, const int* in_sizes, int n_in,
                              void* d_out, int out_size){
    const float* q     = (const float*)d_in[0];
    const float* k     = (const float*)d_in[1];
    const float* v     = (const float*)d_in[2];
    const float* Wq    = (const float*)d_in[3];
    const float* bq    = (const float*)d_in[4];
    const float* Wk    = (const float*)d_in[5];
    const float* bk    = (const float*)d_in[6];
    const float* Wv    = (const float*)d_in[7];
    const float* bv    = (const float*)d_in[8];
    const float* Wproj = (const float*)d_in[9];
    const float* bproj = (const float*)d_in[10];
    const float* Waddq = (const float*)d_in[11];
    const float* baddq = (const float*)d_in[12];
    const float* W1    = (const float*)d_in[13];
    const float* b1    = (const float*)d_in[14];
    const float* W2    = (const float*)d_in[15];
    const float* b2    = (const float*)d_in[16];
    const float* g_pre = (const float*)d_in[17];
    const float* b_pre = (const float*)d_in[18];
    const float* g_nrm = (const float*)d_in[19];
    const float* b_nrm = (const float*)d_in[20];
    float* out = (float*)d_out;

    float* kpool = sym(g_kpool);
    float* vpool = sym(g_vpool);
    float* qf    = sym(g_qf);
    float* kf    = sym(g_kf);
    float* vf    = sym(g_vf);
    float* ao    = sym(g_attno);
    float* fac   = sym(g_fac);
    float* lnb   = sym(g_lnbuf);
    float* xb    = sym(g_xbuf);
    float* h1    = sym(g_h1);
    float* part1 = sym(g_part1);
    float* part2 = sym(g_part2);
    float* part3 = sym(g_part3);

    cudaFuncSetAttribute(flash_kernel, cudaFuncAttributeMaxDynamicSharedMemorySize, FL_SMEM);

    {   // pool k, v -> natural (b,cam,c,kk) layout
        long total = (long)NB*NCAM*DIM*PK;
        int blocks = (int)((total + 255) / 256);
        pool_kernel<<<blocks, 256>>>(k, kpool);
        pool_kernel<<<blocks, 256>>>(v, vpool);
    }
    {   // add_q partials: direct q (ATRANS), per-b batch, split-K x3
        GemmP p = zeroP();
        p.A = q; p.ATR = 1; p.lda = HWQ;
        p.a1 = (long)NCAM*DIM*HWQ;           // per-b stride
        p.B = Waddq; p.ldb = DIM;
        p.C = part1; p.ldc = DIM; p.c1 = (long)HWQ*DIM;
        p.M = HWQ; p.N = DIM; p.K = ND/3; p.D1 = NB;
        p.SPLIT = 3; p.csplit = (long)NB*HWQ*DIM;
        launch_gemm(p, NB);
    }
    {   // qf per (b,cam): direct q (ATRANS)
        GemmP p = zeroP();
        p.A = q; p.ATR = 1; p.lda = HWQ;
        p.a0 = (long)NCAM*DIM*HWQ; p.a1 = (long)DIM*HWQ;
        p.B = Wq; p.ldb = DIM; p.bias = bq;
        p.C = qf; p.ldc = DIM; p.c0 = (long)NCAM*HWQ*DIM; p.c1 = (long)HWQ*DIM;
        p.M = HWQ; p.N = DIM; p.K = DIM; p.D1 = NCAM;
        launch_gemm(p, NB*NCAM);
    }
    {   // kf, vf per (b,cam): pooled natural layout (ATRANS)
        GemmP p = zeroP();
        p.A = kpool; p.ATR = 1; p.lda = PKP;
        p.a0 = (long)NCAM*DIM*PKP; p.a1 = (long)DIM*PKP;
        p.B = Wk; p.ldb = DIM; p.bias = bk;
        p.C = kf; p.ldc = DIM; p.c0 = (long)NCAM*PK*DIM; p.c1 = (long)PK*DIM;
        p.M = PK; p.N = DIM; p.K = DIM; p.D1 = NCAM;
        launch_gemm(p, NB*NCAM);
        p.A = vpool; p.B = Wv; p.bias = bv; p.C = vf;
        launch_gemm(p, NB*NCAM);
    }
    {   // flash attention, per-cam blocks
        dim3 grid((HWQ+127)/128, NB*NHEAD*NCAM);
        flash_kernel<<<grid, 256, FL_SMEM>>>(qf, kf, vf, ao, fac);
    }
    ln1536_kernel<<<NB*HWQ, 256>>>(ao, fac, g_pre, b_pre, lnb);
    {   // proj partials, split-K x3 (row-major A)
        GemmP p = zeroP();
        p.A = lnb; p.lda = ND; p.B = Wproj; p.ldb = DIM;
        p.C = part2; p.ldc = DIM; p.M = NB*HWQ; p.N = DIM;
        p.K = ND/3; p.SPLIT = 3; p.csplit = (long)NB*HWQ*DIM;
        launch_gemm(p, 1);
    }
    {
        long MN = (long)NB*HWQ*DIM;
        reduce_proj_kernel<<<(int)((MN+255)/256), 256>>>(part1, part2, baddq, bproj, xb);
    }
    {   // ffn1 + gelu
        GemmP p = zeroP();
        p.A = xb; p.lda = DIM; p.B = W1; p.ldb = 2*DIM; p.bias = b1; p.gelu = 1;
        p.C = h1; p.ldc = 2*DIM; p.M = NB*HWQ; p.N = 2*DIM; p.K = DIM;
        launch_gemm(p, 1);
    }
    {   // ffn2 partials, split-K x2
        GemmP p = zeroP();
        p.A = h1; p.lda = 2*DIM; p.B = W2; p.ldb = DIM;
        p.C = part3; p.ldc = DIM; p.M = NB*HWQ; p.N = DIM;
        p.K = DIM; p.SPLIT = 2; p.csplit = (long)NB*HWQ*DIM;
        launch_gemm(p, 1);
    }
    final_kernel<<<NB*HWQ, 256>>>(part3, b2, xb, g_nrm, b_nrm, out);
}